// round 11
// baseline (speedup 1.0000x reference)
#include <cuda_runtime.h>
#include <cuda_fp16.h>
#include <math.h>
#include <cstdint>

// ---------------------------------------------------------------------------
// VectorQuantizerEMA: N=32768 vectors, D=256, K=8192 codes
// FP16 mma.sync (fp32 acc) argmin, KSPLIT=8 for wave balance,
// triple-buffered B, fused merge+rerank, fused prologue/tail.
// d_out layout (float32):
//   [0)          out (quant_st NCHW) 8388608
//   [8388608)    loss 1
//   [8388609)    perplexity 1
//   [8388610)    new_cluster_size 8192
//   [8396802)    new_embed 2097152
//   [10493954)   new_ema_embed 2097152
// ---------------------------------------------------------------------------

#define NB      32
#define DD      256
#define HW      1024
#define NN      32768
#define KK      8192

#define OUT_OFF      0
#define LOSS_OFF     8388608
#define PERP_OFF     8388609
#define NCS_OFF      8388610
#define NEWEMB_OFF   8396802
#define NEWEMA_OFF   10493954

#define KSPLIT  8
#define KPS     (KK / KSPLIT)     // 1024 codes per slice
#define KSLOT   (KSPLIT * 4)      // 32 disjoint candidate slots per row
#define NIT     (KPS / 32)        // 32 mainloop iterations

// ---- scratch (device globals; no allocation allowed) ----
__device__ float   g_X[NN * DD];      // fp32 transposed inputs [N,D]
__device__ __half  g_Xf[NN * DD];     // fp16 [N,D]
__device__ float   g_EtF[KK * DD];    // fp32 E^T [K,D]
__device__ __half  g_Ef[KK * DD];     // fp16 E^T [K,D]
__device__ float  g_enorm[KK];
__device__ double g_enormd[KK];
__device__ int   g_idx[NN];
__device__ float g_sv1[NN * KSLOT];   // [row][slot]
__device__ float g_sv2[NN * KSLOT];
__device__ int   g_si1[NN * KSLOT];
__device__ int   g_si2[NN * KSLOT];
__device__ float g_counts[KK];
__device__ float g_invsm[KK];
__device__ float g_scal[4];

// ===========================================================================
// helpers
// ===========================================================================
__device__ __forceinline__ uint32_t smem_to_u32(const void* p) {
    uint32_t a;
    asm("{ .reg .u64 t; cvta.to.shared.u64 t, %1; cvt.u32.u64 %0, t; }"
        : "=r"(a) : "l"(p));
    return a;
}
__device__ __forceinline__ void ldsm4(uint32_t* r, uint32_t addr) {
    asm volatile("ldmatrix.sync.aligned.m8n8.x4.shared.b16 {%0,%1,%2,%3}, [%4];"
                 : "=r"(r[0]), "=r"(r[1]), "=r"(r[2]), "=r"(r[3]) : "r"(addr));
}
__device__ __forceinline__ void mma16816(float* c, const uint32_t* a, const uint32_t* b) {
    asm volatile(
        "mma.sync.aligned.m16n8k16.row.col.f32.f16.f16.f32 "
        "{%0,%1,%2,%3}, {%4,%5,%6,%7}, {%8,%9}, {%0,%1,%2,%3};"
        : "+f"(c[0]), "+f"(c[1]), "+f"(c[2]), "+f"(c[3])
        : "r"(a[0]), "r"(a[1]), "r"(a[2]), "r"(a[3]), "r"(b[0]), "r"(b[1]));
}
__device__ __forceinline__ void cp16(uint32_t dst, const void* src) {
    asm volatile("cp.async.cg.shared.global [%0], [%1], 16;"
                 :: "r"(dst), "l"(src) : "memory");
}
#define CP_COMMIT() asm volatile("cp.async.commit_group;" ::: "memory")

// smem: A [kc(4)][128 rows][128B swizzled] = 64KB ; B [buf(3)][128 codes][128B] = 48KB
#define SMEM_A   0
#define SMEM_B   65536
#define SMEM_TOT 114688

// ---------------------------------------------------------------------------
// K0 (fused prologue): role by blockIdx.
// ---------------------------------------------------------------------------
#define RT_T  8192
#define RT_E  (RT_T + 2048)
#define RT_N  (RT_E + 32)
#define RT_I  (RT_N + 8192)

__global__ void prep_kernel(const float* __restrict__ in,
                            const float* __restrict__ embed,
                            const float* __restrict__ ema,
                            float* __restrict__ out) {
    __shared__ float tile[32][33];
    int bid = blockIdx.x;
    int t = threadIdx.x;
    if (bid < RT_T) {
        int hx = bid & 31, dy = (bid >> 5) & 7, b = bid >> 8;
        int d0 = dy * 32, h0 = hx * 32;
        int tx = t & 31, ty = t >> 5;     // 32 x 8
        const float* src = in + (size_t)b * DD * HW;
#pragma unroll
        for (int i = 0; i < 32; i += 8)
            tile[ty + i][tx] = src[(d0 + ty + i) * HW + h0 + tx];
        __syncthreads();
#pragma unroll
        for (int i = 0; i < 32; i += 8) {
            float v = tile[tx][ty + i];
            size_t o = (size_t)(b * HW + h0 + ty + i) * DD + d0 + tx;
            g_X[o]  = v;
            g_Xf[o] = __float2half_rn(v);
        }
    } else if (bid < RT_E) {
        int rb = bid - RT_T;
        int kx = rb & 255, dy = rb >> 8;
        int k0 = kx * 32, d0 = dy * 32;
        int tx = t & 31, ty = t >> 5;
#pragma unroll
        for (int i = 0; i < 32; i += 8)
            tile[ty + i][tx] = embed[(size_t)(d0 + ty + i) * KK + k0 + tx];
        __syncthreads();
#pragma unroll
        for (int i = 0; i < 32; i += 8) {
            float v = tile[tx][ty + i];
            size_t o = (size_t)(k0 + ty + i) * DD + d0 + tx;
            g_EtF[o] = v;
            g_Ef[o]  = __float2half_rn(v);
        }
    } else if (bid < RT_N) {
        int k = (bid - RT_E) * 256 + t;
        float s = 0.f;
        double sd = 0.0;
#pragma unroll 8
        for (int d = 0; d < DD; d++) {
            float v = embed[(size_t)d * KK + k];
            s = fmaf(v, v, s);
            sd = fma((double)v, (double)v, sd);
        }
        g_enorm[k]  = s;
        g_enormd[k] = sd;
    } else {
        int i = (bid - RT_N) * 256 + t;
        out[NEWEMA_OFF + i] = 0.99f * ema[i];
        if (i < KK)  g_counts[i] = 0.f;
        if (i < 4)   g_scal[i]   = 0.f;
    }
}

// ---------------------------------------------------------------------------
// B-chunk producer: 128 codes x 64 d (fp16) via cp.async into buffer `buf`
// ---------------------------------------------------------------------------
__device__ __forceinline__ void issueB(uint32_t sb, int buf, int c0, int kc, int tid) {
#pragma unroll
    for (int i = 0; i < 4; ++i) {
        int v = tid + i * 256;            // 0..1023
        int code = v >> 3, g = v & 7;
        const void* s = &g_Ef[(size_t)(c0 + code) * DD + kc * 64 + g * 8];
        uint32_t d = sb + SMEM_B + buf * 16384 + code * 128
                   + (uint32_t)((g ^ (code & 7)) << 4);
        cp16(d, s);
    }
    CP_COMMIT();
}

// ---------------------------------------------------------------------------
// K2: fp16 mma.sync argmin (fp32 acc). CTA = 128 rows x 1024-code slice.
// 8 warps (2x4). Triple-buffered B, one barrier per iteration.
// ---------------------------------------------------------------------------
__global__ __launch_bounds__(256, 2) void argmin_mma_kernel() {
    extern __shared__ char smem[];
    uint32_t sb = smem_to_u32(smem);
    int tid  = threadIdx.x;
    int lane = tid & 31, wid = tid >> 5;
    int wm = wid >> 2, wn = wid & 3;
    int mt = blockIdx.x >> 3, slice = blockIdx.x & 7;
    int n0 = mt * 128;
    int cs0 = slice * KPS;

    // ---- stage A via cp.async: 128 rows x 256 d fp16, swizzled ----
#pragma unroll
    for (int i = 0; i < 16; ++i) {
        int v = tid + i * 256;
        int kc = v >> 10;
        int u = v & 1023;
        int row = u >> 3, g = u & 7;
        uint32_t off = sb + SMEM_A + kc * 16384 + row * 128
                     + (uint32_t)((g ^ (row & 7)) << 4);
        cp16(off, &g_Xf[(size_t)(n0 + row) * DD + kc * 64 + g * 8]);
    }
    CP_COMMIT();

    issueB(sb, 0, cs0, 0, tid);
    issueB(sb, 1, cs0, 1, tid);

    float acc[4][4][4];
#pragma unroll
    for (int m = 0; m < 4; ++m)
#pragma unroll
        for (int n = 0; n < 4; ++n)
#pragma unroll
            for (int q = 0; q < 4; ++q) acc[m][n][q] = 0.f;

    float t1v[8], t2v[8];
    int   t1i[8], t2i[8];
#pragma unroll
    for (int s = 0; s < 8; ++s) { t1v[s] = 3.4e38f; t2v[s] = 3.4e38f; t1i[s] = 0; t2i[s] = 0; }

    int j   = lane >> 3, rwi = lane & 7;
    int arow = wm * 64 + rwi + ((j & 1) << 3);
    int agsel = j >> 1;
    int arx  = arow & 7;
    uint32_t aBase = sb + SMEM_A + (uint32_t)arow * 128;
    int crow = wn * 32 + ((j >> 1) << 3) + rwi;
    int bgsel = j & 1;
    int crx  = crow & 7;
    uint32_t bBase = sb + SMEM_B + (uint32_t)crow * 128;

    int tid4 = lane & 3;

#pragma unroll 1
    for (int it = 0; it < NIT; ++it) {
        int kc = it & 3;
        int buf = it % 3;
        if (it < NIT - 1) asm volatile("cp.async.wait_group 1;" ::: "memory");
        else              asm volatile("cp.async.wait_group 0;" ::: "memory");
        __syncthreads();
        if (it + 2 < NIT) {
            int it2 = it + 2;
            issueB(sb, it2 % 3, cs0 + (it2 >> 2) * 128, it2 & 3, tid);
        }

#pragma unroll
        for (int kk = 0; kk < 4; ++kk) {
            uint32_t ah[4][4], bh[2][4];
            uint32_t ga = (uint32_t)(((2 * kk + agsel) ^ arx) << 4);
            uint32_t gb = (uint32_t)(((2 * kk + bgsel) ^ crx) << 4);
#pragma unroll
            for (int m = 0; m < 4; ++m)
                ldsm4(ah[m], aBase + kc * 16384 + m * 2048 + ga);
#pragma unroll
            for (int np = 0; np < 2; ++np)
                ldsm4(bh[np], bBase + buf * 16384 + np * 2048 + gb);
#pragma unroll
            for (int m = 0; m < 4; ++m)
#pragma unroll
                for (int n = 0; n < 4; ++n)
                    mma16816(acc[m][n], ah[m], &bh[n >> 1][(n & 1) * 2]);
        }

        if (kc == 3) {
            int nt = it >> 2;
            int cb = cs0 + nt * 128 + wn * 32 + tid4 * 2;
#pragma unroll
            for (int m = 0; m < 4; ++m) {
#pragma unroll
                for (int n = 0; n < 4; ++n) {
                    int c = cb + n * 8;
                    float2 en = *(const float2*)&g_enorm[c];
                    float d0 = fmaf(-2.f, acc[m][n][0], en.x);
                    float d1 = fmaf(-2.f, acc[m][n][1], en.y);
                    float d2 = fmaf(-2.f, acc[m][n][2], en.x);
                    float d3 = fmaf(-2.f, acc[m][n][3], en.y);
                    int s0 = m * 2, s1 = m * 2 + 1;
                    if (d0 < t1v[s0]) { t2v[s0] = t1v[s0]; t2i[s0] = t1i[s0]; t1v[s0] = d0; t1i[s0] = c; }
                    else if (d0 < t2v[s0]) { t2v[s0] = d0; t2i[s0] = c; }
                    if (d1 < t1v[s0]) { t2v[s0] = t1v[s0]; t2i[s0] = t1i[s0]; t1v[s0] = d1; t1i[s0] = c + 1; }
                    else if (d1 < t2v[s0]) { t2v[s0] = d1; t2i[s0] = c + 1; }
                    if (d2 < t1v[s1]) { t2v[s1] = t1v[s1]; t2i[s1] = t1i[s1]; t1v[s1] = d2; t1i[s1] = c; }
                    else if (d2 < t2v[s1]) { t2v[s1] = d2; t2i[s1] = c; }
                    if (d3 < t1v[s1]) { t2v[s1] = t1v[s1]; t2i[s1] = t1i[s1]; t1v[s1] = d3; t1i[s1] = c + 1; }
                    else if (d3 < t2v[s1]) { t2v[s1] = d3; t2i[s1] = c + 1; }
#pragma unroll
                    for (int q = 0; q < 4; ++q) acc[m][n][q] = 0.f;
                }
            }
        }
    }

#pragma unroll
    for (int s = 0; s < 8; ++s) {
        float v1 = t1v[s], v2 = t2v[s];
        int   i1 = t1i[s], i2 = t2i[s];
#pragma unroll
        for (int off = 1; off <= 2; off <<= 1) {
            float ov1 = __shfl_xor_sync(0xffffffffu, v1, off);
            int   oi1 = __shfl_xor_sync(0xffffffffu, i1, off);
            float ov2 = __shfl_xor_sync(0xffffffffu, v2, off);
            int   oi2 = __shfl_xor_sync(0xffffffffu, i2, off);
            if (ov1 < v1 || (ov1 == v1 && oi1 < i1)) {
                float nv2; int ni2;
                if (v1 < ov2 || (v1 == ov2 && i1 < oi2)) { nv2 = v1; ni2 = i1; }
                else { nv2 = ov2; ni2 = oi2; }
                v1 = ov1; i1 = oi1; v2 = nv2; i2 = ni2;
            } else {
                if (ov1 < v2 || (ov1 == v2 && oi1 < i2)) { v2 = ov1; i2 = oi1; }
            }
        }
        if (tid4 == 0) {
            int grp = lane >> 2;
            int row = n0 + wm * 64 + (s >> 1) * 16 + (s & 1) * 8 + grp;
            int slot = slice * 4 + wn;
            g_sv1[row * KSLOT + slot] = v1;
            g_si1[row * KSLOT + slot] = i1;
            g_sv2[row * KSLOT + slot] = v2;
            g_si2[row * KSLOT + slot] = i2;
        }
    }
}

// ---------------------------------------------------------------------------
// K2c: fused merge + exact fp64 rerank (1 warp per row).
// Each lane owns one slot's (top1, top2); 4 warp-min rounds extract the
// global top-4 (indices unique across slots); fp64 picks the true argmin.
// ---------------------------------------------------------------------------
__global__ void rerank_kernel() {
    int wid  = threadIdx.x >> 5;
    int lane = threadIdx.x & 31;
    int row  = blockIdx.x * 8 + wid;

    float v1 = g_sv1[row * KSLOT + lane];
    float v2 = g_sv2[row * KSLOT + lane];
    int   i1 = g_si1[row * KSLOT + lane];
    int   i2 = g_si2[row * KSLOT + lane];   // per-slot: (v1,i1) <= (v2,i2)

    int cand[4];
#pragma unroll
    for (int c = 0; c < 4; ++c) {
        float bv = v1; int bi = i1;
#pragma unroll
        for (int o = 16; o; o >>= 1) {
            float ov = __shfl_xor_sync(0xffffffffu, bv, o);
            int   oi = __shfl_xor_sync(0xffffffffu, bi, o);
            if (ov < bv || (ov == bv && oi < bi)) { bv = ov; bi = oi; }
        }
        cand[c] = bi;
        if (v1 == bv && i1 == bi) { v1 = v2; i1 = i2; v2 = 3.4e38f; i2 = 0x7fffffff; }
    }

    const float4* xp = (const float4*)&g_X[(size_t)row * DD + lane * 8];
    float4 xa = xp[0], xb = xp[1];
    double s[4];
#pragma unroll
    for (int c = 0; c < 4; ++c) {
        const float4* ep = (const float4*)&g_EtF[(size_t)cand[c] * DD + lane * 8];
        float4 ea = ep[0], eb = ep[1];
        double a = 0.0;
        a = fma((double)xa.x, (double)ea.x, a);
        a = fma((double)xa.y, (double)ea.y, a);
        a = fma((double)xa.z, (double)ea.z, a);
        a = fma((double)xa.w, (double)ea.w, a);
        a = fma((double)xb.x, (double)eb.x, a);
        a = fma((double)xb.y, (double)eb.y, a);
        a = fma((double)xb.z, (double)eb.z, a);
        a = fma((double)xb.w, (double)eb.w, a);
        s[c] = a;
    }
#pragma unroll
    for (int o = 16; o; o >>= 1) {
#pragma unroll
        for (int c = 0; c < 4; ++c)
            s[c] += __shfl_down_sync(0xffffffffu, s[c], o);
    }
    if (lane == 0) {
        double bv = g_enormd[cand[0]] - 2.0 * s[0]; int bi = cand[0];
#pragma unroll
        for (int c = 1; c < 4; ++c) {
            double d = g_enormd[cand[c]] - 2.0 * s[c];
            if (d < bv || (d == bv && cand[c] < bi)) { bv = d; bi = cand[c]; }
        }
        g_idx[row] = bi;
    }
}

// ---------------------------------------------------------------------------
// K4 (fused tail): role by blockIdx.
//   [0, 256)        gather quantize -> out (NCHW) + loss
//   [256, 33024)    scatter dw into new_ema_embed + counts
// ---------------------------------------------------------------------------
__global__ void tail_kernel(const float* __restrict__ inputs,
                            const float* __restrict__ embed,
                            float* __restrict__ out) {
    __shared__ int sidx[HW];
    __shared__ float sred[8];
    int bid = blockIdx.x;
    int t = threadIdx.x;

    if (bid < 256) {
        int b  = bid >> 3;
        int d0 = (bid & 7) * 32;

        for (int i = t; i < HW; i += 256) sidx[i] = g_idx[b * HW + i];
        __syncthreads();

        float lsum = 0.f;
        for (int d = d0; d < d0 + 32; d++) {
            const float* erow = embed + (size_t)d * KK;
            const float* irow = inputs + (size_t)b * DD * HW + (size_t)d * HW;
            float* orow       = out + OUT_OFF + (size_t)b * DD * HW + (size_t)d * HW;
#pragma unroll
            for (int hw = t; hw < HW; hw += 256) {
                float q = erow[sidx[hw]];
                float x = irow[hw];
                orow[hw] = q;
                float df = q - x;
                lsum = fmaf(df, df, lsum);
            }
        }
#pragma unroll
        for (int o = 16; o; o >>= 1) lsum += __shfl_down_sync(0xffffffffu, lsum, o);
        if ((t & 31) == 0) sred[t >> 5] = lsum;
        __syncthreads();
        if (t == 0) {
            float s = 0.f;
#pragma unroll
            for (int i = 0; i < 8; i++) s += sred[i];
            atomicAdd(&g_scal[0], s);
        }
    } else {
        int n = bid - 256;
        int d = t;
        int id = g_idx[n];
        float x = g_X[(size_t)n * DD + d];
        atomicAdd(&out[NEWEMA_OFF + (size_t)d * KK + id], 0.01f * x);
        if (d == 0) atomicAdd(&g_counts[id], 1.0f);
    }
}

// ---------------------------------------------------------------------------
// K6: finalize scalars + new_cluster_size + 1/smoothed
// ---------------------------------------------------------------------------
__global__ void finalize_kernel(const float* __restrict__ cs, float* __restrict__ out) {
    __shared__ float sh[32];
    __shared__ float s_n;
    int t = threadIdx.x;
    float ncs_loc[8];
    float nsum = 0.f, psum = 0.f;
#pragma unroll
    for (int i = 0; i < 8; i++) {
        int k = t + i * 1024;
        float c = g_counts[k];
        float v = cs[k] * 0.99f + 0.01f * c;
        out[NCS_OFF + k] = v;
        ncs_loc[i] = v;
        nsum += v;
        float p = c * (1.0f / 32768.0f);
        psum += p * logf(p + 1e-10f);
    }
#pragma unroll
    for (int o = 16; o; o >>= 1) nsum += __shfl_down_sync(0xffffffffu, nsum, o);
    if ((t & 31) == 0) sh[t >> 5] = nsum;
    __syncthreads();
    if (t < 32) {
        float v = sh[t];
#pragma unroll
        for (int o = 16; o; o >>= 1) v += __shfl_down_sync(0xffffffffu, v, o);
        if (t == 0) s_n = v;
    }
    __syncthreads();
    float n = s_n;
#pragma unroll
    for (int i = 0; i < 8; i++) {
        int k = t + i * 1024;
        float v = ncs_loc[i];
        g_invsm[k] = (n + v * 1e-5f) / (n * (v + 1e-5f));
    }
    __syncthreads();
#pragma unroll
    for (int o = 16; o; o >>= 1) psum += __shfl_down_sync(0xffffffffu, psum, o);
    if ((t & 31) == 0) sh[t >> 5] = psum;
    __syncthreads();
    if (t == 0) {
        float p = 0.f;
#pragma unroll
        for (int i = 0; i < 32; i++) p += sh[i];
        out[LOSS_OFF] = 0.25f * g_scal[0] * (1.0f / 8388608.0f);
        out[PERP_OFF] = expf(-p);
    }
}

// ---------------------------------------------------------------------------
// K7: new_embed = new_ema_embed * (1/smoothed)
// ---------------------------------------------------------------------------
__global__ void newembed_kernel(float* __restrict__ out) {
    int i = blockIdx.x * 256 + threadIdx.x;
    int k = i & (KK - 1);
    out[NEWEMB_OFF + i] = out[NEWEMA_OFF + i] * g_invsm[k];
}

// ---------------------------------------------------------------------------
extern "C" void kernel_launch(void* const* d_in, const int* in_sizes, int n_in,
                              void* d_out, int out_size) {
    const float* inputs = (const float*)d_in[0];
    const float* embed  = (const float*)d_in[1];
    const float* cs     = (const float*)d_in[2];
    const float* ema    = (const float*)d_in[3];
    float* out = (float*)d_out;
    (void)in_sizes; (void)n_in; (void)out_size;

    cudaFuncSetAttribute(argmin_mma_kernel,
                         cudaFuncAttributeMaxDynamicSharedMemorySize, SMEM_TOT);

    prep_kernel<<<RT_I, 256>>>(inputs, embed, ema, out);
    argmin_mma_kernel<<<(NN / 128) * KSPLIT, 256, SMEM_TOT>>>();
    rerank_kernel<<<NN / 8, 256>>>();
    tail_kernel<<<256 + NN, 256>>>(inputs, embed, out);
    finalize_kernel<<<1, 1024>>>(cs, out);
    newembed_kernel<<<(DD * KK) / 256, 256>>>(out);
}

// round 14
// speedup vs baseline: 1.0383x; 1.0383x over previous
#include <cuda_runtime.h>
#include <cuda_fp16.h>
#include <cuda.h>
#include <math.h>
#include <cstdint>

// ---------------------------------------------------------------------------
// VectorQuantizerEMA: N=32768 vectors, D=256, K=8192 codes
// FP16 mma.sync (fp32 acc) argmin with TMA (cp.async.bulk.tensor) staging,
// triple-buffered B, fused merge+rerank, fused prologue/tail.
// d_out layout (float32):
//   [0)          out (quant_st NCHW) 8388608
//   [8388608)    loss 1
//   [8388609)    perplexity 1
//   [8388610)    new_cluster_size 8192
//   [8396802)    new_embed 2097152
//   [10493954)   new_ema_embed 2097152
// ---------------------------------------------------------------------------

#define NB      32
#define DD      256
#define HW      1024
#define NN      32768
#define KK      8192

#define OUT_OFF      0
#define LOSS_OFF     8388608
#define PERP_OFF     8388609
#define NCS_OFF      8388610
#define NEWEMB_OFF   8396802
#define NEWEMA_OFF   10493954

#define KSPLIT  4
#define KPS     (KK / KSPLIT)     // 2048 codes per slice
#define KSLOT   (KSPLIT * 4)      // 16 disjoint candidate slots per row
#define NIT     64                // 16 code-tiles x 4 d-chunks

// ---- scratch (device globals; no allocation allowed) ----
__device__ float   g_X[NN * DD];                 // fp32 transposed inputs [N,D]
__device__ __align__(128) __half g_Xf[NN * DD];  // fp16 [N,D] (TMA source)
__device__ float   g_EtF[KK * DD];               // fp32 E^T [K,D]
__device__ __align__(128) __half g_Ef[KK * DD];  // fp16 E^T [K,D] (TMA source)
__device__ float  g_enorm[KK];
__device__ double g_enormd[KK];
__device__ int   g_idx[NN];
__device__ float g_sv1[NN * KSLOT];   // [row][slot]
__device__ float g_sv2[NN * KSLOT];
__device__ int   g_si1[NN * KSLOT];
__device__ int   g_si2[NN * KSLOT];
__device__ float g_counts[KK];
__device__ float g_invsm[KK];
__device__ float g_scal[4];

// ===========================================================================
// helpers
// ===========================================================================
__device__ __forceinline__ uint32_t smem_to_u32(const void* p) {
    uint32_t a;
    asm("{ .reg .u64 t; cvta.to.shared.u64 t, %1; cvt.u32.u64 %0, t; }"
        : "=r"(a) : "l"(p));
    return a;
}
__device__ __forceinline__ void ldsm4(uint32_t* r, uint32_t addr) {
    asm volatile("ldmatrix.sync.aligned.m8n8.x4.shared.b16 {%0,%1,%2,%3}, [%4];"
                 : "=r"(r[0]), "=r"(r[1]), "=r"(r[2]), "=r"(r[3]) : "r"(addr));
}
__device__ __forceinline__ void mma16816(float* c, const uint32_t* a, const uint32_t* b) {
    asm volatile(
        "mma.sync.aligned.m16n8k16.row.col.f32.f16.f16.f32 "
        "{%0,%1,%2,%3}, {%4,%5,%6,%7}, {%8,%9}, {%0,%1,%2,%3};"
        : "+f"(c[0]), "+f"(c[1]), "+f"(c[2]), "+f"(c[3])
        : "r"(a[0]), "r"(a[1]), "r"(a[2]), "r"(a[3]), "r"(b[0]), "r"(b[1]));
}
#define MBARRIER_INIT(mbar, cnt) \
    asm volatile("mbarrier.init.shared.b64 [%0], %1;" \
        :: "r"((uint32_t)(mbar)), "r"((uint32_t)(cnt)) : "memory")
#define MBARRIER_EXPECT_TX(mbar, bytes) \
    asm volatile("mbarrier.arrive.expect_tx.shared.b64 _, [%0], %1;" \
        :: "r"((uint32_t)(mbar)), "r"((uint32_t)(bytes)) : "memory")
#define MBARRIER_WAIT_PARITY(mbar, par) do { \
    uint32_t _mbar = (uint32_t)(mbar); \
    uint32_t _p = (uint32_t)(par); \
    uint32_t _done; \
    asm volatile("{\n\t.reg .pred p;\n\t" \
        "mbarrier.try_wait.parity.acquire.cta.shared::cta.b64 p, [%1], %2;\n\t" \
        "selp.b32 %0, 1, 0, p;\n\t}" : "=r"(_done) : "r"(_mbar), "r"(_p) : "memory"); \
    if (!_done) { \
        asm volatile("{\n\t.reg .pred P1;\n\t" \
            "WL_%=:\n\t" \
            "mbarrier.try_wait.parity.acquire.cta.shared::cta.b64 P1, [%0], %1, 0x989680;\n\t" \
            "@P1 bra.uni WD_%=;\n\t" \
            "bra.uni WL_%=;\n\t" \
            "WD_%=:\n\t}" :: "r"(_mbar), "r"(_p) : "memory"); \
    } \
} while (0)
__device__ __forceinline__ void tma_load_2d(uint32_t smem_addr, const void* tmap,
                                            int cx, int cy, uint32_t mbar) {
    asm volatile(
        "cp.async.bulk.tensor.2d.shared::cta.global.tile.mbarrier::complete_tx::bytes "
        "[%0], [%1, {%2, %3}], [%4];"
        :: "r"(smem_addr), "l"(tmap), "r"(cx), "r"(cy), "r"(mbar)
        : "memory");
}

// smem: mbarriers [0,32); A at 1024 (64KB); B at 66560 (3 x 16KB)
#define SM_MB    0
#define SMEM_A   1024
#define SMEM_B   66560
#define SMEM_TOT 115712

// ---------------------------------------------------------------------------
// K0 (fused prologue): role by blockIdx.
// ---------------------------------------------------------------------------
#define RT_T  8192
#define RT_E  (RT_T + 2048)
#define RT_N  (RT_E + 32)
#define RT_I  (RT_N + 8192)

__global__ void prep_kernel(const float* __restrict__ in,
                            const float* __restrict__ embed,
                            const float* __restrict__ ema,
                            float* __restrict__ out) {
    __shared__ float tile[32][33];
    int bid = blockIdx.x;
    int t = threadIdx.x;
    if (bid < RT_T) {
        int hx = bid & 31, dy = (bid >> 5) & 7, b = bid >> 8;
        int d0 = dy * 32, h0 = hx * 32;
        int tx = t & 31, ty = t >> 5;     // 32 x 8
        const float* src = in + (size_t)b * DD * HW;
#pragma unroll
        for (int i = 0; i < 32; i += 8)
            tile[ty + i][tx] = src[(d0 + ty + i) * HW + h0 + tx];
        __syncthreads();
#pragma unroll
        for (int i = 0; i < 32; i += 8) {
            float v = tile[tx][ty + i];
            size_t o = (size_t)(b * HW + h0 + ty + i) * DD + d0 + tx;
            g_X[o]  = v;
            g_Xf[o] = __float2half_rn(v);
        }
    } else if (bid < RT_E) {
        int rb = bid - RT_T;
        int kx = rb & 255, dy = rb >> 8;
        int k0 = kx * 32, d0 = dy * 32;
        int tx = t & 31, ty = t >> 5;
#pragma unroll
        for (int i = 0; i < 32; i += 8)
            tile[ty + i][tx] = embed[(size_t)(d0 + ty + i) * KK + k0 + tx];
        __syncthreads();
#pragma unroll
        for (int i = 0; i < 32; i += 8) {
            float v = tile[tx][ty + i];
            size_t o = (size_t)(k0 + ty + i) * DD + d0 + tx;
            g_EtF[o] = v;
            g_Ef[o]  = __float2half_rn(v);
        }
    } else if (bid < RT_N) {
        int k = (bid - RT_E) * 256 + t;
        float s = 0.f;
        double sd = 0.0;
#pragma unroll 8
        for (int d = 0; d < DD; d++) {
            float v = embed[(size_t)d * KK + k];
            s = fmaf(v, v, s);
            sd = fma((double)v, (double)v, sd);
        }
        g_enorm[k]  = s;
        g_enormd[k] = sd;
    } else {
        int i = (bid - RT_N) * 256 + t;
        out[NEWEMA_OFF + i] = 0.99f * ema[i];
        if (i < KK)  g_counts[i] = 0.f;
        if (i < 4)   g_scal[i]   = 0.f;
    }
}

// ---------------------------------------------------------------------------
// K2: fp16 mma.sync argmin (fp32 acc), TMA staging. CTA = 128 rows x 2048-code
// slice. 8 warps (2x4). Triple-buffered B, one barrier per iteration.
// ---------------------------------------------------------------------------
__global__ __launch_bounds__(256, 2) void argmin_mma_kernel(
        const __grid_constant__ CUtensorMap tmA,
        const __grid_constant__ CUtensorMap tmB) {
    extern __shared__ char smem[];
    uint32_t sb = smem_to_u32(smem);
    int tid  = threadIdx.x;
    int lane = tid & 31, wid = tid >> 5;
    int wm = wid >> 2, wn = wid & 3;
    int mt = blockIdx.x >> 2, slice = blockIdx.x & 3;
    int n0 = mt * 128;
    int cs0 = slice * KPS;

    if (tid == 0) {
        MBARRIER_INIT(sb + SM_MB + 0,  1);   // B buf 0
        MBARRIER_INIT(sb + SM_MB + 8,  1);   // B buf 1
        MBARRIER_INIT(sb + SM_MB + 16, 1);   // B buf 2
        MBARRIER_INIT(sb + SM_MB + 24, 1);   // A
    }
    __syncthreads();

    if (tid == 0) {
        // A: 4 TMA boxes (64d x 128 rows), all on one mbarrier
        MBARRIER_EXPECT_TX(sb + SM_MB + 24, 65536);
#pragma unroll
        for (int kc = 0; kc < 4; ++kc)
            tma_load_2d(sb + SMEM_A + kc * 16384, &tmA, kc * 64, n0, sb + SM_MB + 24);
        // B: prefetch iterations 0, 1
        MBARRIER_EXPECT_TX(sb + SM_MB + 0, 16384);
        tma_load_2d(sb + SMEM_B + 0, &tmB, 0, cs0, sb + SM_MB + 0);
        MBARRIER_EXPECT_TX(sb + SM_MB + 8, 16384);
        tma_load_2d(sb + SMEM_B + 16384, &tmB, 64, cs0, sb + SM_MB + 8);
    }

    float acc[4][4][4];
#pragma unroll
    for (int m = 0; m < 4; ++m)
#pragma unroll
        for (int n = 0; n < 4; ++n)
#pragma unroll
            for (int q = 0; q < 4; ++q) acc[m][n][q] = 0.f;

    float t1v[8], t2v[8];
    int   t1i[8], t2i[8];
#pragma unroll
    for (int s = 0; s < 8; ++s) { t1v[s] = 3.4e38f; t2v[s] = 3.4e38f; t1i[s] = 0; t2i[s] = 0; }

    int j   = lane >> 3, rwi = lane & 7;
    int arow = wm * 64 + rwi + ((j & 1) << 3);
    int agsel = j >> 1;
    int arx  = arow & 7;
    uint32_t aBase = sb + SMEM_A + (uint32_t)arow * 128;
    int crow = wn * 32 + ((j >> 1) << 3) + rwi;
    int bgsel = j & 1;
    int crx  = crow & 7;
    uint32_t bBase = sb + SMEM_B + (uint32_t)crow * 128;

    int tid4 = lane & 3;

    // wait for A
    MBARRIER_WAIT_PARITY(sb + SM_MB + 24, 0);

#pragma unroll 1
    for (int it = 0; it < NIT; ++it) {
        int kc = it & 3;
        int buf = it % 3;
        // wait for this buffer's fill #(it/3)
        MBARRIER_WAIT_PARITY(sb + SM_MB + buf * 8, (it / 3) & 1);
        __syncthreads();       // all warps done reading iteration it-1
        if (tid == 0 && it + 2 < NIT) {
            int it2 = it + 2;
            int b2 = it2 % 3;
            MBARRIER_EXPECT_TX(sb + SM_MB + b2 * 8, 16384);
            tma_load_2d(sb + SMEM_B + b2 * 16384, &tmB,
                        (it2 & 3) * 64, cs0 + (it2 >> 2) * 128, sb + SM_MB + b2 * 8);
        }

#pragma unroll
        for (int kk = 0; kk < 4; ++kk) {
            uint32_t ah[4][4], bh[2][4];
            uint32_t ga = (uint32_t)(((2 * kk + agsel) ^ arx) << 4);
            uint32_t gb = (uint32_t)(((2 * kk + bgsel) ^ crx) << 4);
#pragma unroll
            for (int m = 0; m < 4; ++m)
                ldsm4(ah[m], aBase + kc * 16384 + m * 2048 + ga);
#pragma unroll
            for (int np = 0; np < 2; ++np)
                ldsm4(bh[np], bBase + buf * 16384 + np * 2048 + gb);
#pragma unroll
            for (int m = 0; m < 4; ++m)
#pragma unroll
                for (int n = 0; n < 4; ++n)
                    mma16816(acc[m][n], ah[m], &bh[n >> 1][(n & 1) * 2]);
        }

        if (kc == 3) {
            int nt = it >> 2;
            int cb = cs0 + nt * 128 + wn * 32 + tid4 * 2;
#pragma unroll
            for (int m = 0; m < 4; ++m) {
#pragma unroll
                for (int n = 0; n < 4; ++n) {
                    int c = cb + n * 8;
                    float2 en = *(const float2*)&g_enorm[c];
                    float d0 = fmaf(-2.f, acc[m][n][0], en.x);
                    float d1 = fmaf(-2.f, acc[m][n][1], en.y);
                    float d2 = fmaf(-2.f, acc[m][n][2], en.x);
                    float d3 = fmaf(-2.f, acc[m][n][3], en.y);
                    int s0 = m * 2, s1 = m * 2 + 1;
                    if (d0 < t1v[s0]) { t2v[s0] = t1v[s0]; t2i[s0] = t1i[s0]; t1v[s0] = d0; t1i[s0] = c; }
                    else if (d0 < t2v[s0]) { t2v[s0] = d0; t2i[s0] = c; }
                    if (d1 < t1v[s0]) { t2v[s0] = t1v[s0]; t2i[s0] = t1i[s0]; t1v[s0] = d1; t1i[s0] = c + 1; }
                    else if (d1 < t2v[s0]) { t2v[s0] = d1; t2i[s0] = c + 1; }
                    if (d2 < t1v[s1]) { t2v[s1] = t1v[s1]; t2i[s1] = t1i[s1]; t1v[s1] = d2; t1i[s1] = c; }
                    else if (d2 < t2v[s1]) { t2v[s1] = d2; t2i[s1] = c; }
                    if (d3 < t1v[s1]) { t2v[s1] = t1v[s1]; t2i[s1] = t1i[s1]; t1v[s1] = d3; t1i[s1] = c + 1; }
                    else if (d3 < t2v[s1]) { t2v[s1] = d3; t2i[s1] = c + 1; }
#pragma unroll
                    for (int q = 0; q < 4; ++q) acc[m][n][q] = 0.f;
                }
            }
        }
    }

#pragma unroll
    for (int s = 0; s < 8; ++s) {
        float v1 = t1v[s], v2 = t2v[s];
        int   i1 = t1i[s], i2 = t2i[s];
#pragma unroll
        for (int off = 1; off <= 2; off <<= 1) {
            float ov1 = __shfl_xor_sync(0xffffffffu, v1, off);
            int   oi1 = __shfl_xor_sync(0xffffffffu, i1, off);
            float ov2 = __shfl_xor_sync(0xffffffffu, v2, off);
            int   oi2 = __shfl_xor_sync(0xffffffffu, i2, off);
            if (ov1 < v1 || (ov1 == v1 && oi1 < i1)) {
                float nv2; int ni2;
                if (v1 < ov2 || (v1 == ov2 && i1 < oi2)) { nv2 = v1; ni2 = i1; }
                else { nv2 = ov2; ni2 = oi2; }
                v1 = ov1; i1 = oi1; v2 = nv2; i2 = ni2;
            } else {
                if (ov1 < v2 || (ov1 == v2 && oi1 < i2)) { v2 = ov1; i2 = oi1; }
            }
        }
        if (tid4 == 0) {
            int grp = lane >> 2;
            int row = n0 + wm * 64 + (s >> 1) * 16 + (s & 1) * 8 + grp;
            int slot = slice * 4 + wn;
            g_sv1[row * KSLOT + slot] = v1;
            g_si1[row * KSLOT + slot] = i1;
            g_sv2[row * KSLOT + slot] = v2;
            g_si2[row * KSLOT + slot] = i2;
        }
    }
}

// ---------------------------------------------------------------------------
// K2c: fused merge + exact fp64 rerank (1 warp per row).
// ---------------------------------------------------------------------------
__global__ void rerank_kernel() {
    int wid  = threadIdx.x >> 5;
    int lane = threadIdx.x & 31;
    int row  = blockIdx.x * 8 + wid;

    float v; int idx;
    if (lane < 16) { v = g_sv1[row * KSLOT + lane];        idx = g_si1[row * KSLOT + lane]; }
    else           { v = g_sv2[row * KSLOT + (lane - 16)]; idx = g_si2[row * KSLOT + (lane - 16)]; }

    int cand[4];
#pragma unroll
    for (int c = 0; c < 4; ++c) {
        float bv = v; int bi = idx;
#pragma unroll
        for (int o = 16; o; o >>= 1) {
            float ov = __shfl_xor_sync(0xffffffffu, bv, o);
            int   oi = __shfl_xor_sync(0xffffffffu, bi, o);
            if (ov < bv || (ov == bv && oi < bi)) { bv = ov; bi = oi; }
        }
        cand[c] = bi;
        if (v == bv && idx == bi) v = 3.4e38f;   // retire winner
    }

    const float4* xp = (const float4*)&g_X[(size_t)row * DD + lane * 8];
    float4 xa = xp[0], xb = xp[1];
    double s[4];
#pragma unroll
    for (int c = 0; c < 4; ++c) {
        const float4* ep = (const float4*)&g_EtF[(size_t)cand[c] * DD + lane * 8];
        float4 ea = ep[0], eb = ep[1];
        double a = 0.0;
        a = fma((double)xa.x, (double)ea.x, a);
        a = fma((double)xa.y, (double)ea.y, a);
        a = fma((double)xa.z, (double)ea.z, a);
        a = fma((double)xa.w, (double)ea.w, a);
        a = fma((double)xb.x, (double)eb.x, a);
        a = fma((double)xb.y, (double)eb.y, a);
        a = fma((double)xb.z, (double)eb.z, a);
        a = fma((double)xb.w, (double)eb.w, a);
        s[c] = a;
    }
#pragma unroll
    for (int o = 16; o; o >>= 1) {
#pragma unroll
        for (int c = 0; c < 4; ++c)
            s[c] += __shfl_down_sync(0xffffffffu, s[c], o);
    }
    if (lane == 0) {
        double bv = g_enormd[cand[0]] - 2.0 * s[0]; int bi = cand[0];
#pragma unroll
        for (int c = 1; c < 4; ++c) {
            double d = g_enormd[cand[c]] - 2.0 * s[c];
            if (d < bv || (d == bv && cand[c] < bi)) { bv = d; bi = cand[c]; }
        }
        g_idx[row] = bi;
    }
}

// ---------------------------------------------------------------------------
// K4 (fused tail): gather + scatter, role by blockIdx.
// ---------------------------------------------------------------------------
__global__ void tail_kernel(const float* __restrict__ inputs,
                            const float* __restrict__ embed,
                            float* __restrict__ out) {
    __shared__ int sidx[HW];
    __shared__ float sred[8];
    int bid = blockIdx.x;
    int t = threadIdx.x;

    if (bid < 256) {
        int b  = bid >> 3;
        int d0 = (bid & 7) * 32;

        for (int i = t; i < HW; i += 256) sidx[i] = g_idx[b * HW + i];
        __syncthreads();

        float lsum = 0.f;
        for (int d = d0; d < d0 + 32; d++) {
            const float* erow = embed + (size_t)d * KK;
            const float* irow = inputs + (size_t)b * DD * HW + (size_t)d * HW;
            float* orow       = out + OUT_OFF + (size_t)b * DD * HW + (size_t)d * HW;
#pragma unroll
            for (int hw = t; hw < HW; hw += 256) {
                float q = erow[sidx[hw]];
                float x = irow[hw];
                orow[hw] = q;
                float df = q - x;
                lsum = fmaf(df, df, lsum);
            }
        }
#pragma unroll
        for (int o = 16; o; o >>= 1) lsum += __shfl_down_sync(0xffffffffu, lsum, o);
        if ((t & 31) == 0) sred[t >> 5] = lsum;
        __syncthreads();
        if (t == 0) {
            float s = 0.f;
#pragma unroll
            for (int i = 0; i < 8; i++) s += sred[i];
            atomicAdd(&g_scal[0], s);
        }
    } else {
        int n = bid - 256;
        int d = t;
        int id = g_idx[n];
        float x = g_X[(size_t)n * DD + d];
        atomicAdd(&out[NEWEMA_OFF + (size_t)d * KK + id], 0.01f * x);
        if (d == 0) atomicAdd(&g_counts[id], 1.0f);
    }
}

// ---------------------------------------------------------------------------
// K6: finalize scalars + new_cluster_size + 1/smoothed
// ---------------------------------------------------------------------------
__global__ void finalize_kernel(const float* __restrict__ cs, float* __restrict__ out) {
    __shared__ float sh[32];
    __shared__ float s_n;
    int t = threadIdx.x;
    float ncs_loc[8];
    float nsum = 0.f, psum = 0.f;
#pragma unroll
    for (int i = 0; i < 8; i++) {
        int k = t + i * 1024;
        float c = g_counts[k];
        float v = cs[k] * 0.99f + 0.01f * c;
        out[NCS_OFF + k] = v;
        ncs_loc[i] = v;
        nsum += v;
        float p = c * (1.0f / 32768.0f);
        psum += p * logf(p + 1e-10f);
    }
#pragma unroll
    for (int o = 16; o; o >>= 1) nsum += __shfl_down_sync(0xffffffffu, nsum, o);
    if ((t & 31) == 0) sh[t >> 5] = nsum;
    __syncthreads();
    if (t < 32) {
        float v = sh[t];
#pragma unroll
        for (int o = 16; o; o >>= 1) v += __shfl_down_sync(0xffffffffu, v, o);
        if (t == 0) s_n = v;
    }
    __syncthreads();
    float n = s_n;
#pragma unroll
    for (int i = 0; i < 8; i++) {
        int k = t + i * 1024;
        float v = ncs_loc[i];
        g_invsm[k] = (n + v * 1e-5f) / (n * (v + 1e-5f));
    }
    __syncthreads();
#pragma unroll
    for (int o = 16; o; o >>= 1) psum += __shfl_down_sync(0xffffffffu, psum, o);
    if ((t & 31) == 0) sh[t >> 5] = psum;
    __syncthreads();
    if (t == 0) {
        float p = 0.f;
#pragma unroll
        for (int i = 0; i < 32; i++) p += sh[i];
        out[LOSS_OFF] = 0.25f * g_scal[0] * (1.0f / 8388608.0f);
        out[PERP_OFF] = expf(-p);
    }
}

// ---------------------------------------------------------------------------
// K7: new_embed = new_ema_embed * (1/smoothed)
// ---------------------------------------------------------------------------
__global__ void newembed_kernel(float* __restrict__ out) {
    int i = blockIdx.x * 256 + threadIdx.x;
    int k = i & (KK - 1);
    out[NEWEMB_OFF + i] = out[NEWEMA_OFF + i] * g_invsm[k];
}

// ---------------------------------------------------------------------------
typedef CUresult (*PFN_tmec)(CUtensorMap*, CUtensorMapDataType, cuuint32_t,
                             void*, const cuuint64_t*, const cuuint64_t*,
                             const cuuint32_t*, const cuuint32_t*,
                             CUtensorMapInterleave, CUtensorMapSwizzle,
                             CUtensorMapL2promotion, CUtensorMapFloatOOBfill);

extern "C" void kernel_launch(void* const* d_in, const int* in_sizes, int n_in,
                              void* d_out, int out_size) {
    const float* inputs = (const float*)d_in[0];
    const float* embed  = (const float*)d_in[1];
    const float* cs     = (const float*)d_in[2];
    const float* ema    = (const float*)d_in[3];
    float* out = (float*)d_out;
    (void)in_sizes; (void)n_in; (void)out_size;

    // --- build TMA tensormaps (host-side; baked into graph at capture) ---
    void* fnp = nullptr;
    cudaDriverEntryPointQueryResult qr;
    cudaGetDriverEntryPointByVersion("cuTensorMapEncodeTiled", &fnp, 12000,
                                     cudaEnableDefault, &qr);
    PFN_tmec encode = (PFN_tmec)fnp;

    void *pXf = nullptr, *pEf = nullptr;
    cudaGetSymbolAddress(&pXf, g_Xf);
    cudaGetSymbolAddress(&pEf, g_Ef);

    CUtensorMap tmA, tmB;
    {
        cuuint64_t dims[2]  = {256, 32768};
        cuuint64_t strides[1] = {512};
        cuuint32_t box[2]   = {64, 128};
        cuuint32_t es[2]    = {1, 1};
        encode(&tmA, CU_TENSOR_MAP_DATA_TYPE_FLOAT16, 2, pXf, dims, strides,
               box, es, CU_TENSOR_MAP_INTERLEAVE_NONE, CU_TENSOR_MAP_SWIZZLE_128B,
               CU_TENSOR_MAP_L2_PROMOTION_L2_128B, CU_TENSOR_MAP_FLOAT_OOB_FILL_NONE);
    }
    {
        cuuint64_t dims[2]  = {256, 8192};
        cuuint64_t strides[1] = {512};
        cuuint32_t box[2]   = {64, 128};
        cuuint32_t es[2]    = {1, 1};
        encode(&tmB, CU_TENSOR_MAP_DATA_TYPE_FLOAT16, 2, pEf, dims, strides,
               box, es, CU_TENSOR_MAP_INTERLEAVE_NONE, CU_TENSOR_MAP_SWIZZLE_128B,
               CU_TENSOR_MAP_L2_PROMOTION_L2_128B, CU_TENSOR_MAP_FLOAT_OOB_FILL_NONE);
    }

    cudaFuncSetAttribute(argmin_mma_kernel,
                         cudaFuncAttributeMaxDynamicSharedMemorySize, SMEM_TOT);

    prep_kernel<<<RT_I, 256>>>(inputs, embed, ema, out);
    argmin_mma_kernel<<<(NN / 128) * KSPLIT, 256, SMEM_TOT>>>(tmA, tmB);
    rerank_kernel<<<NN / 8, 256>>>();
    tail_kernel<<<256 + NN, 256>>>(inputs, embed, out);
    finalize_kernel<<<1, 1024>>>(cs, out);
    newembed_kernel<<<(DD * KK) / 256, 256>>>(out);
}

// round 15
// speedup vs baseline: 1.3106x; 1.2622x over previous
#include <cuda_runtime.h>
#include <cuda_fp16.h>
#include <cuda.h>
#include <math.h>
#include <cstdint>

// ---------------------------------------------------------------------------
// VectorQuantizerEMA: N=32768 vectors, D=256, K=8192 codes
// FP16 mma.sync (fp32 acc) argmin with TMA staging, triple-buffered B,
// fused merge+rerank+scatter (compensated fp32), fused prologue, gather tail.
// d_out layout (float32):
//   [0)          out (quant_st NCHW) 8388608
//   [8388608)    loss 1
//   [8388609)    perplexity 1
//   [8388610)    new_cluster_size 8192
//   [8396802)    new_embed 2097152
//   [10493954)   new_ema_embed 2097152
// ---------------------------------------------------------------------------

#define NB      32
#define DD      256
#define HW      1024
#define NN      32768
#define KK      8192

#define OUT_OFF      0
#define LOSS_OFF     8388608
#define PERP_OFF     8388609
#define NCS_OFF      8388610
#define NEWEMB_OFF   8396802
#define NEWEMA_OFF   10493954

#define KSPLIT  4
#define KPS     (KK / KSPLIT)     // 2048 codes per slice
#define KSLOT   (KSPLIT * 4)      // 16 disjoint candidate slots per row
#define NIT     64                // 16 code-tiles x 4 d-chunks

// ---- scratch (device globals; no allocation allowed) ----
__device__ float   g_X[NN * DD];                 // fp32 transposed inputs [N,D]
__device__ __align__(128) __half g_Xf[NN * DD];  // fp16 [N,D] (TMA source)
__device__ float   g_EtF[KK * DD];               // fp32 E^T [K,D]
__device__ __align__(128) __half g_Ef[KK * DD];  // fp16 E^T [K,D] (TMA source)
__device__ float  g_enorm[KK];
__device__ double g_enormd[KK];
__device__ int   g_idx[NN];
__device__ float g_sv1[NN * KSLOT];   // [row][slot]
__device__ float g_sv2[NN * KSLOT];
__device__ int   g_si1[NN * KSLOT];
__device__ int   g_si2[NN * KSLOT];
__device__ float g_counts[KK];
__device__ float g_invsm[KK];
__device__ float g_scal[4];

// ===========================================================================
// helpers
// ===========================================================================
__device__ __forceinline__ uint32_t smem_to_u32(const void* p) {
    uint32_t a;
    asm("{ .reg .u64 t; cvta.to.shared.u64 t, %1; cvt.u32.u64 %0, t; }"
        : "=r"(a) : "l"(p));
    return a;
}
__device__ __forceinline__ void ldsm4(uint32_t* r, uint32_t addr) {
    asm volatile("ldmatrix.sync.aligned.m8n8.x4.shared.b16 {%0,%1,%2,%3}, [%4];"
                 : "=r"(r[0]), "=r"(r[1]), "=r"(r[2]), "=r"(r[3]) : "r"(addr));
}
__device__ __forceinline__ void mma16816(float* c, const uint32_t* a, const uint32_t* b) {
    asm volatile(
        "mma.sync.aligned.m16n8k16.row.col.f32.f16.f16.f32 "
        "{%0,%1,%2,%3}, {%4,%5,%6,%7}, {%8,%9}, {%0,%1,%2,%3};"
        : "+f"(c[0]), "+f"(c[1]), "+f"(c[2]), "+f"(c[3])
        : "r"(a[0]), "r"(a[1]), "r"(a[2]), "r"(a[3]), "r"(b[0]), "r"(b[1]));
}
#define MBARRIER_INIT(mbar, cnt) \
    asm volatile("mbarrier.init.shared.b64 [%0], %1;" \
        :: "r"((uint32_t)(mbar)), "r"((uint32_t)(cnt)) : "memory")
#define MBARRIER_EXPECT_TX(mbar, bytes) \
    asm volatile("mbarrier.arrive.expect_tx.shared.b64 _, [%0], %1;" \
        :: "r"((uint32_t)(mbar)), "r"((uint32_t)(bytes)) : "memory")
#define MBARRIER_WAIT_PARITY(mbar, par) do { \
    uint32_t _mbar = (uint32_t)(mbar); \
    uint32_t _p = (uint32_t)(par); \
    uint32_t _done; \
    asm volatile("{\n\t.reg .pred p;\n\t" \
        "mbarrier.try_wait.parity.acquire.cta.shared::cta.b64 p, [%1], %2;\n\t" \
        "selp.b32 %0, 1, 0, p;\n\t}" : "=r"(_done) : "r"(_mbar), "r"(_p) : "memory"); \
    if (!_done) { \
        asm volatile("{\n\t.reg .pred P1;\n\t" \
            "WL_%=:\n\t" \
            "mbarrier.try_wait.parity.acquire.cta.shared::cta.b64 P1, [%0], %1, 0x989680;\n\t" \
            "@P1 bra.uni WD_%=;\n\t" \
            "bra.uni WL_%=;\n\t" \
            "WD_%=:\n\t}" :: "r"(_mbar), "r"(_p) : "memory"); \
    } \
} while (0)
__device__ __forceinline__ void tma_load_2d(uint32_t smem_addr, const void* tmap,
                                            int cx, int cy, uint32_t mbar) {
    asm volatile(
        "cp.async.bulk.tensor.2d.shared::cta.global.tile.mbarrier::complete_tx::bytes "
        "[%0], [%1, {%2, %3}], [%4];"
        :: "r"(smem_addr), "l"(tmap), "r"(cx), "r"(cy), "r"(mbar)
        : "memory");
}

// smem: mbarriers [0,32); A at 1024 (64KB); B at 66560 (3 x 16KB)
#define SM_MB    0
#define SMEM_A   1024
#define SMEM_B   66560
#define SMEM_TOT 115712

// ---------------------------------------------------------------------------
// K0 (fused prologue): role by blockIdx.
// ---------------------------------------------------------------------------
#define RT_T  8192
#define RT_E  (RT_T + 2048)
#define RT_N  (RT_E + 32)
#define RT_I  (RT_N + 8192)

__global__ void prep_kernel(const float* __restrict__ in,
                            const float* __restrict__ embed,
                            const float* __restrict__ ema,
                            float* __restrict__ out) {
    __shared__ float tile[32][33];
    int bid = blockIdx.x;
    int t = threadIdx.x;
    if (bid < RT_T) {
        int hx = bid & 31, dy = (bid >> 5) & 7, b = bid >> 8;
        int d0 = dy * 32, h0 = hx * 32;
        int tx = t & 31, ty = t >> 5;     // 32 x 8
        const float* src = in + (size_t)b * DD * HW;
#pragma unroll
        for (int i = 0; i < 32; i += 8)
            tile[ty + i][tx] = src[(d0 + ty + i) * HW + h0 + tx];
        __syncthreads();
#pragma unroll
        for (int i = 0; i < 32; i += 8) {
            float v = tile[tx][ty + i];
            size_t o = (size_t)(b * HW + h0 + ty + i) * DD + d0 + tx;
            g_X[o]  = v;
            g_Xf[o] = __float2half_rn(v);
        }
    } else if (bid < RT_E) {
        int rb = bid - RT_T;
        int kx = rb & 255, dy = rb >> 8;
        int k0 = kx * 32, d0 = dy * 32;
        int tx = t & 31, ty = t >> 5;
#pragma unroll
        for (int i = 0; i < 32; i += 8)
            tile[ty + i][tx] = embed[(size_t)(d0 + ty + i) * KK + k0 + tx];
        __syncthreads();
#pragma unroll
        for (int i = 0; i < 32; i += 8) {
            float v = tile[tx][ty + i];
            size_t o = (size_t)(k0 + ty + i) * DD + d0 + tx;
            g_EtF[o] = v;
            g_Ef[o]  = __float2half_rn(v);
        }
    } else if (bid < RT_N) {
        int k = (bid - RT_E) * 256 + t;
        float s = 0.f;
        double sd = 0.0;
#pragma unroll 8
        for (int d = 0; d < DD; d++) {
            float v = embed[(size_t)d * KK + k];
            s = fmaf(v, v, s);
            sd = fma((double)v, (double)v, sd);
        }
        g_enorm[k]  = s;
        g_enormd[k] = sd;
    } else {
        int i = (bid - RT_N) * 256 + t;
        out[NEWEMA_OFF + i] = 0.99f * ema[i];
        if (i < KK)  g_counts[i] = 0.f;
        if (i < 4)   g_scal[i]   = 0.f;
    }
}

// ---------------------------------------------------------------------------
// K2: fp16 mma.sync argmin (fp32 acc), TMA staging. CTA = 128 rows x 2048-code
// slice. 8 warps (2x4). Triple-buffered B, one barrier per iteration.
// ---------------------------------------------------------------------------
__global__ __launch_bounds__(256, 2) void argmin_mma_kernel(
        const __grid_constant__ CUtensorMap tmA,
        const __grid_constant__ CUtensorMap tmB) {
    extern __shared__ char smem[];
    uint32_t sb = smem_to_u32(smem);
    int tid  = threadIdx.x;
    int lane = tid & 31, wid = tid >> 5;
    int wm = wid >> 2, wn = wid & 3;
    int mt = blockIdx.x >> 2, slice = blockIdx.x & 3;
    int n0 = mt * 128;
    int cs0 = slice * KPS;

    if (tid == 0) {
        MBARRIER_INIT(sb + SM_MB + 0,  1);   // B buf 0
        MBARRIER_INIT(sb + SM_MB + 8,  1);   // B buf 1
        MBARRIER_INIT(sb + SM_MB + 16, 1);   // B buf 2
        MBARRIER_INIT(sb + SM_MB + 24, 1);   // A
    }
    __syncthreads();

    if (tid == 0) {
        MBARRIER_EXPECT_TX(sb + SM_MB + 24, 65536);
#pragma unroll
        for (int kc = 0; kc < 4; ++kc)
            tma_load_2d(sb + SMEM_A + kc * 16384, &tmA, kc * 64, n0, sb + SM_MB + 24);
        MBARRIER_EXPECT_TX(sb + SM_MB + 0, 16384);
        tma_load_2d(sb + SMEM_B + 0, &tmB, 0, cs0, sb + SM_MB + 0);
        MBARRIER_EXPECT_TX(sb + SM_MB + 8, 16384);
        tma_load_2d(sb + SMEM_B + 16384, &tmB, 64, cs0, sb + SM_MB + 8);
    }

    float acc[4][4][4];
#pragma unroll
    for (int m = 0; m < 4; ++m)
#pragma unroll
        for (int n = 0; n < 4; ++n)
#pragma unroll
            for (int q = 0; q < 4; ++q) acc[m][n][q] = 0.f;

    float t1v[8], t2v[8];
    int   t1i[8], t2i[8];
#pragma unroll
    for (int s = 0; s < 8; ++s) { t1v[s] = 3.4e38f; t2v[s] = 3.4e38f; t1i[s] = 0; t2i[s] = 0; }

    int j   = lane >> 3, rwi = lane & 7;
    int arow = wm * 64 + rwi + ((j & 1) << 3);
    int agsel = j >> 1;
    int arx  = arow & 7;
    uint32_t aBase = sb + SMEM_A + (uint32_t)arow * 128;
    int crow = wn * 32 + ((j >> 1) << 3) + rwi;
    int bgsel = j & 1;
    int crx  = crow & 7;
    uint32_t bBase = sb + SMEM_B + (uint32_t)crow * 128;

    int tid4 = lane & 3;

    MBARRIER_WAIT_PARITY(sb + SM_MB + 24, 0);

#pragma unroll 1
    for (int it = 0; it < NIT; ++it) {
        int kc = it & 3;
        int buf = it % 3;
        MBARRIER_WAIT_PARITY(sb + SM_MB + buf * 8, (it / 3) & 1);
        __syncthreads();
        if (tid == 0 && it + 2 < NIT) {
            int it2 = it + 2;
            int b2 = it2 % 3;
            MBARRIER_EXPECT_TX(sb + SM_MB + b2 * 8, 16384);
            tma_load_2d(sb + SMEM_B + b2 * 16384, &tmB,
                        (it2 & 3) * 64, cs0 + (it2 >> 2) * 128, sb + SM_MB + b2 * 8);
        }

#pragma unroll
        for (int kk = 0; kk < 4; ++kk) {
            uint32_t ah[4][4], bh[2][4];
            uint32_t ga = (uint32_t)(((2 * kk + agsel) ^ arx) << 4);
            uint32_t gb = (uint32_t)(((2 * kk + bgsel) ^ crx) << 4);
#pragma unroll
            for (int m = 0; m < 4; ++m)
                ldsm4(ah[m], aBase + kc * 16384 + m * 2048 + ga);
#pragma unroll
            for (int np = 0; np < 2; ++np)
                ldsm4(bh[np], bBase + buf * 16384 + np * 2048 + gb);
#pragma unroll
            for (int m = 0; m < 4; ++m)
#pragma unroll
                for (int n = 0; n < 4; ++n)
                    mma16816(acc[m][n], ah[m], &bh[n >> 1][(n & 1) * 2]);
        }

        if (kc == 3) {
            int nt = it >> 2;
            int cb = cs0 + nt * 128 + wn * 32 + tid4 * 2;
#pragma unroll
            for (int m = 0; m < 4; ++m) {
#pragma unroll
                for (int n = 0; n < 4; ++n) {
                    int c = cb + n * 8;
                    float2 en = *(const float2*)&g_enorm[c];
                    float d0 = fmaf(-2.f, acc[m][n][0], en.x);
                    float d1 = fmaf(-2.f, acc[m][n][1], en.y);
                    float d2 = fmaf(-2.f, acc[m][n][2], en.x);
                    float d3 = fmaf(-2.f, acc[m][n][3], en.y);
                    int s0 = m * 2, s1 = m * 2 + 1;
                    if (d0 < t1v[s0]) { t2v[s0] = t1v[s0]; t2i[s0] = t1i[s0]; t1v[s0] = d0; t1i[s0] = c; }
                    else if (d0 < t2v[s0]) { t2v[s0] = d0; t2i[s0] = c; }
                    if (d1 < t1v[s0]) { t2v[s0] = t1v[s0]; t2i[s0] = t1i[s0]; t1v[s0] = d1; t1i[s0] = c + 1; }
                    else if (d1 < t2v[s0]) { t2v[s0] = d1; t2i[s0] = c + 1; }
                    if (d2 < t1v[s1]) { t2v[s1] = t1v[s1]; t2i[s1] = t1i[s1]; t1v[s1] = d2; t1i[s1] = c; }
                    else if (d2 < t2v[s1]) { t2v[s1] = d2; t2i[s1] = c; }
                    if (d3 < t1v[s1]) { t2v[s1] = t1v[s1]; t2i[s1] = t1i[s1]; t1v[s1] = d3; t1i[s1] = c + 1; }
                    else if (d3 < t2v[s1]) { t2v[s1] = d3; t2i[s1] = c + 1; }
#pragma unroll
                    for (int q = 0; q < 4; ++q) acc[m][n][q] = 0.f;
                }
            }
        }
    }

#pragma unroll
    for (int s = 0; s < 8; ++s) {
        float v1 = t1v[s], v2 = t2v[s];
        int   i1 = t1i[s], i2 = t2i[s];
#pragma unroll
        for (int off = 1; off <= 2; off <<= 1) {
            float ov1 = __shfl_xor_sync(0xffffffffu, v1, off);
            int   oi1 = __shfl_xor_sync(0xffffffffu, i1, off);
            float ov2 = __shfl_xor_sync(0xffffffffu, v2, off);
            int   oi2 = __shfl_xor_sync(0xffffffffu, i2, off);
            if (ov1 < v1 || (ov1 == v1 && oi1 < i1)) {
                float nv2; int ni2;
                if (v1 < ov2 || (v1 == ov2 && i1 < oi2)) { nv2 = v1; ni2 = i1; }
                else { nv2 = ov2; ni2 = oi2; }
                v1 = ov1; i1 = oi1; v2 = nv2; i2 = ni2;
            } else {
                if (ov1 < v2 || (ov1 == v2 && oi1 < i2)) { v2 = ov1; i2 = oi1; }
            }
        }
        if (tid4 == 0) {
            int grp = lane >> 2;
            int row = n0 + wm * 64 + (s >> 1) * 16 + (s & 1) * 8 + grp;
            int slot = slice * 4 + wn;
            g_sv1[row * KSLOT + slot] = v1;
            g_si1[row * KSLOT + slot] = i1;
            g_sv2[row * KSLOT + slot] = v2;
            g_si2[row * KSLOT + slot] = i2;
        }
    }
}

// ---------------------------------------------------------------------------
// K2c: fused merge + compensated-fp32 rerank + dw scatter (1 warp per row).
// TwoProd (fmaf) + separate error sum gives the dot to ~1e-6 relative;
// final compare in fp64 against g_enormd. Then the warp scatters its row's
// 0.01*x into new_ema_embed (x already in registers) + counts.
// ---------------------------------------------------------------------------
__global__ void rerank_kernel(float* __restrict__ out) {
    int wid  = threadIdx.x >> 5;
    int lane = threadIdx.x & 31;
    int row  = blockIdx.x * 8 + wid;

    float v; int idx;
    if (lane < 16) { v = g_sv1[row * KSLOT + lane];        idx = g_si1[row * KSLOT + lane]; }
    else           { v = g_sv2[row * KSLOT + (lane - 16)]; idx = g_si2[row * KSLOT + (lane - 16)]; }

    int cand[4];
#pragma unroll
    for (int c = 0; c < 4; ++c) {
        float bv = v; int bi = idx;
#pragma unroll
        for (int o = 16; o; o >>= 1) {
            float ov = __shfl_xor_sync(0xffffffffu, bv, o);
            int   oi = __shfl_xor_sync(0xffffffffu, bi, o);
            if (ov < bv || (ov == bv && oi < bi)) { bv = ov; bi = oi; }
        }
        cand[c] = bi;
        if (v == bv && idx == bi) v = 3.4e38f;   // retire winner
    }

    const float4* xp = (const float4*)&g_X[(size_t)row * DD + lane * 8];
    float4 xa = xp[0], xb = xp[1];
    float Sp[4], Se[4];
#pragma unroll
    for (int c = 0; c < 4; ++c) {
        const float4* ep = (const float4*)&g_EtF[(size_t)cand[c] * DD + lane * 8];
        float4 ea = ep[0], eb = ep[1];
        float p, sp = 0.f, se = 0.f;
        p = xa.x * ea.x; se += fmaf(xa.x, ea.x, -p); sp += p;
        p = xa.y * ea.y; se += fmaf(xa.y, ea.y, -p); sp += p;
        p = xa.z * ea.z; se += fmaf(xa.z, ea.z, -p); sp += p;
        p = xa.w * ea.w; se += fmaf(xa.w, ea.w, -p); sp += p;
        p = xb.x * eb.x; se += fmaf(xb.x, eb.x, -p); sp += p;
        p = xb.y * eb.y; se += fmaf(xb.y, eb.y, -p); sp += p;
        p = xb.z * eb.z; se += fmaf(xb.z, eb.z, -p); sp += p;
        p = xb.w * eb.w; se += fmaf(xb.w, eb.w, -p); sp += p;
        Sp[c] = sp; Se[c] = se;
    }
#pragma unroll
    for (int o = 16; o; o >>= 1) {
#pragma unroll
        for (int c = 0; c < 4; ++c) {
            Sp[c] += __shfl_down_sync(0xffffffffu, Sp[c], o);
            Se[c] += __shfl_down_sync(0xffffffffu, Se[c], o);
        }
    }
    int bi = 0;
    if (lane == 0) {
        double bv = 1e300;
        bi = cand[0];
#pragma unroll
        for (int c = 0; c < 4; ++c) {
            double d = g_enormd[cand[c]] - 2.0 * ((double)Sp[c] + (double)Se[c]);
            if (d < bv || (d == bv && cand[c] < bi)) { bv = d; bi = cand[c]; }
        }
        g_idx[row] = bi;
        atomicAdd(&g_counts[bi], 1.0f);
    }
    bi = __shfl_sync(0xffffffffu, bi, 0);

    // fused dw scatter: this warp holds x[row][lane*8 .. lane*8+7]
    int d0 = lane * 8;
    float* base = out + NEWEMA_OFF + bi;
    atomicAdd(base + (size_t)(d0 + 0) * KK, 0.01f * xa.x);
    atomicAdd(base + (size_t)(d0 + 1) * KK, 0.01f * xa.y);
    atomicAdd(base + (size_t)(d0 + 2) * KK, 0.01f * xa.z);
    atomicAdd(base + (size_t)(d0 + 3) * KK, 0.01f * xa.w);
    atomicAdd(base + (size_t)(d0 + 4) * KK, 0.01f * xb.x);
    atomicAdd(base + (size_t)(d0 + 5) * KK, 0.01f * xb.y);
    atomicAdd(base + (size_t)(d0 + 6) * KK, 0.01f * xb.z);
    atomicAdd(base + (size_t)(d0 + 7) * KK, 0.01f * xb.w);
}

// ---------------------------------------------------------------------------
// K4: gather quantize -> out (NCHW), accumulate e_latent_loss
// ---------------------------------------------------------------------------
__global__ void gather_kernel(const float* __restrict__ inputs,
                              const float* __restrict__ embed,
                              float* __restrict__ out) {
    __shared__ int sidx[HW];
    __shared__ float sred[8];
    int b  = blockIdx.x >> 3;
    int d0 = (blockIdx.x & 7) * 32;
    int t  = threadIdx.x;

    for (int i = t; i < HW; i += 256) sidx[i] = g_idx[b * HW + i];
    __syncthreads();

    float lsum = 0.f;
    for (int d = d0; d < d0 + 32; d++) {
        const float* erow = embed + (size_t)d * KK;
        const float* irow = inputs + (size_t)b * DD * HW + (size_t)d * HW;
        float* orow       = out + OUT_OFF + (size_t)b * DD * HW + (size_t)d * HW;
#pragma unroll
        for (int hw = t; hw < HW; hw += 256) {
            float q = erow[sidx[hw]];
            float x = irow[hw];
            orow[hw] = q;
            float df = q - x;
            lsum = fmaf(df, df, lsum);
        }
    }
#pragma unroll
    for (int o = 16; o; o >>= 1) lsum += __shfl_down_sync(0xffffffffu, lsum, o);
    if ((t & 31) == 0) sred[t >> 5] = lsum;
    __syncthreads();
    if (t == 0) {
        float s = 0.f;
#pragma unroll
        for (int i = 0; i < 8; i++) s += sred[i];
        atomicAdd(&g_scal[0], s);
    }
}

// ---------------------------------------------------------------------------
// K6: finalize scalars + new_cluster_size + 1/smoothed
// ---------------------------------------------------------------------------
__global__ void finalize_kernel(const float* __restrict__ cs, float* __restrict__ out) {
    __shared__ float sh[32];
    __shared__ float s_n;
    int t = threadIdx.x;
    float ncs_loc[8];
    float nsum = 0.f, psum = 0.f;
#pragma unroll
    for (int i = 0; i < 8; i++) {
        int k = t + i * 1024;
        float c = g_counts[k];
        float v = cs[k] * 0.99f + 0.01f * c;
        out[NCS_OFF + k] = v;
        ncs_loc[i] = v;
        nsum += v;
        float p = c * (1.0f / 32768.0f);
        psum += p * logf(p + 1e-10f);
    }
#pragma unroll
    for (int o = 16; o; o >>= 1) nsum += __shfl_down_sync(0xffffffffu, nsum, o);
    if ((t & 31) == 0) sh[t >> 5] = nsum;
    __syncthreads();
    if (t < 32) {
        float v = sh[t];
#pragma unroll
        for (int o = 16; o; o >>= 1) v += __shfl_down_sync(0xffffffffu, v, o);
        if (t == 0) s_n = v;
    }
    __syncthreads();
    float n = s_n;
#pragma unroll
    for (int i = 0; i < 8; i++) {
        int k = t + i * 1024;
        float v = ncs_loc[i];
        g_invsm[k] = (n + v * 1e-5f) / (n * (v + 1e-5f));
    }
    __syncthreads();
#pragma unroll
    for (int o = 16; o; o >>= 1) psum += __shfl_down_sync(0xffffffffu, psum, o);
    if ((t & 31) == 0) sh[t >> 5] = psum;
    __syncthreads();
    if (t == 0) {
        float p = 0.f;
#pragma unroll
        for (int i = 0; i < 32; i++) p += sh[i];
        out[LOSS_OFF] = 0.25f * g_scal[0] * (1.0f / 8388608.0f);
        out[PERP_OFF] = expf(-p);
    }
}

// ---------------------------------------------------------------------------
// K7: new_embed = new_ema_embed * (1/smoothed)
// ---------------------------------------------------------------------------
__global__ void newembed_kernel(float* __restrict__ out) {
    int i = blockIdx.x * 256 + threadIdx.x;
    int k = i & (KK - 1);
    out[NEWEMB_OFF + i] = out[NEWEMA_OFF + i] * g_invsm[k];
}

// ---------------------------------------------------------------------------
typedef CUresult (*PFN_tmec)(CUtensorMap*, CUtensorMapDataType, cuuint32_t,
                             void*, const cuuint64_t*, const cuuint64_t*,
                             const cuuint32_t*, const cuuint32_t*,
                             CUtensorMapInterleave, CUtensorMapSwizzle,
                             CUtensorMapL2promotion, CUtensorMapFloatOOBfill);

extern "C" void kernel_launch(void* const* d_in, const int* in_sizes, int n_in,
                              void* d_out, int out_size) {
    const float* inputs = (const float*)d_in[0];
    const float* embed  = (const float*)d_in[1];
    const float* cs     = (const float*)d_in[2];
    const float* ema    = (const float*)d_in[3];
    float* out = (float*)d_out;
    (void)in_sizes; (void)n_in; (void)out_size;

    // --- build TMA tensormaps (host-side; baked into graph at capture) ---
    void* fnp = nullptr;
    cudaDriverEntryPointQueryResult qr;
    cudaGetDriverEntryPointByVersion("cuTensorMapEncodeTiled", &fnp, 12000,
                                     cudaEnableDefault, &qr);
    PFN_tmec encode = (PFN_tmec)fnp;

    void *pXf = nullptr, *pEf = nullptr;
    cudaGetSymbolAddress(&pXf, g_Xf);
    cudaGetSymbolAddress(&pEf, g_Ef);

    CUtensorMap tmA, tmB;
    {
        cuuint64_t dims[2]  = {256, 32768};
        cuuint64_t strides[1] = {512};
        cuuint32_t box[2]   = {64, 128};
        cuuint32_t es[2]    = {1, 1};
        encode(&tmA, CU_TENSOR_MAP_DATA_TYPE_FLOAT16, 2, pXf, dims, strides,
               box, es, CU_TENSOR_MAP_INTERLEAVE_NONE, CU_TENSOR_MAP_SWIZZLE_128B,
               CU_TENSOR_MAP_L2_PROMOTION_L2_128B, CU_TENSOR_MAP_FLOAT_OOB_FILL_NONE);
    }
    {
        cuuint64_t dims[2]  = {256, 8192};
        cuuint64_t strides[1] = {512};
        cuuint32_t box[2]   = {64, 128};
        cuuint32_t es[2]    = {1, 1};
        encode(&tmB, CU_TENSOR_MAP_DATA_TYPE_FLOAT16, 2, pEf, dims, strides,
               box, es, CU_TENSOR_MAP_INTERLEAVE_NONE, CU_TENSOR_MAP_SWIZZLE_128B,
               CU_TENSOR_MAP_L2_PROMOTION_L2_128B, CU_TENSOR_MAP_FLOAT_OOB_FILL_NONE);
    }

    cudaFuncSetAttribute(argmin_mma_kernel,
                         cudaFuncAttributeMaxDynamicSharedMemorySize, SMEM_TOT);

    prep_kernel<<<RT_I, 256>>>(inputs, embed, ema, out);
    argmin_mma_kernel<<<(NN / 128) * KSPLIT, 256, SMEM_TOT>>>(tmA, tmB);
    rerank_kernel<<<NN / 8, 256>>>(out);
    gather_kernel<<<256, 256>>>(inputs, embed, out);
    finalize_kernel<<<1, 1024>>>(cs, out);
    newembed_kernel<<<(DD * KK) / 256, 256>>>(out);
}

// round 16
// speedup vs baseline: 1.3339x; 1.0178x over previous
#include <cuda_runtime.h>
#include <cuda_fp16.h>
#include <cuda.h>
#include <math.h>
#include <cstdint>

// ---------------------------------------------------------------------------
// VectorQuantizerEMA: N=32768 vectors, D=256, K=8192 codes
// FP16 mma.sync (fp32 acc) argmin with TMA staging, triple-buffered B,
// fused merge+rerank+scatter+loss, fused prologue, parallel gather.
// d_out layout (float32):
//   [0)          out (quant_st NCHW) 8388608
//   [8388608)    loss 1
//   [8388609)    perplexity 1
//   [8388610)    new_cluster_size 8192
//   [8396802)    new_embed 2097152
//   [10493954)   new_ema_embed 2097152
// ---------------------------------------------------------------------------

#define NB      32
#define DD      256
#define HW      1024
#define NN      32768
#define KK      8192

#define OUT_OFF      0
#define LOSS_OFF     8388608
#define PERP_OFF     8388609
#define NCS_OFF      8388610
#define NEWEMB_OFF   8396802
#define NEWEMA_OFF   10493954

#define KSPLIT  4
#define KPS     (KK / KSPLIT)     // 2048 codes per slice
#define KSLOT   (KSPLIT * 4)      // 16 disjoint candidate slots per row
#define NIT     64                // 16 code-tiles x 4 d-chunks

// ---- scratch (device globals; no allocation allowed) ----
__device__ float   g_X[NN * DD];                 // fp32 transposed inputs [N,D]
__device__ __align__(128) __half g_Xf[NN * DD];  // fp16 [N,D] (TMA source)
__device__ float   g_EtF[KK * DD];               // fp32 E^T [K,D]
__device__ __align__(128) __half g_Ef[KK * DD];  // fp16 E^T [K,D] (TMA source)
__device__ float  g_enorm[KK];
__device__ double g_enormd[KK];
__device__ int   g_idx[NN];
__device__ float g_sv1[NN * KSLOT];   // [row][slot]
__device__ float g_sv2[NN * KSLOT];
__device__ int   g_si1[NN * KSLOT];
__device__ int   g_si2[NN * KSLOT];
__device__ float g_counts[KK];
__device__ float g_invsm[KK];
__device__ float g_scal[4];

// ===========================================================================
// helpers
// ===========================================================================
__device__ __forceinline__ uint32_t smem_to_u32(const void* p) {
    uint32_t a;
    asm("{ .reg .u64 t; cvta.to.shared.u64 t, %1; cvt.u32.u64 %0, t; }"
        : "=r"(a) : "l"(p));
    return a;
}
__device__ __forceinline__ void ldsm4(uint32_t* r, uint32_t addr) {
    asm volatile("ldmatrix.sync.aligned.m8n8.x4.shared.b16 {%0,%1,%2,%3}, [%4];"
                 : "=r"(r[0]), "=r"(r[1]), "=r"(r[2]), "=r"(r[3]) : "r"(addr));
}
__device__ __forceinline__ void mma16816(float* c, const uint32_t* a, const uint32_t* b) {
    asm volatile(
        "mma.sync.aligned.m16n8k16.row.col.f32.f16.f16.f32 "
        "{%0,%1,%2,%3}, {%4,%5,%6,%7}, {%8,%9}, {%0,%1,%2,%3};"
        : "+f"(c[0]), "+f"(c[1]), "+f"(c[2]), "+f"(c[3])
        : "r"(a[0]), "r"(a[1]), "r"(a[2]), "r"(a[3]), "r"(b[0]), "r"(b[1]));
}
#define MBARRIER_INIT(mbar, cnt) \
    asm volatile("mbarrier.init.shared.b64 [%0], %1;" \
        :: "r"((uint32_t)(mbar)), "r"((uint32_t)(cnt)) : "memory")
#define MBARRIER_EXPECT_TX(mbar, bytes) \
    asm volatile("mbarrier.arrive.expect_tx.shared.b64 _, [%0], %1;" \
        :: "r"((uint32_t)(mbar)), "r"((uint32_t)(bytes)) : "memory")
#define MBARRIER_WAIT_PARITY(mbar, par) do { \
    uint32_t _mbar = (uint32_t)(mbar); \
    uint32_t _p = (uint32_t)(par); \
    uint32_t _done; \
    asm volatile("{\n\t.reg .pred p;\n\t" \
        "mbarrier.try_wait.parity.acquire.cta.shared::cta.b64 p, [%1], %2;\n\t" \
        "selp.b32 %0, 1, 0, p;\n\t}" : "=r"(_done) : "r"(_mbar), "r"(_p) : "memory"); \
    if (!_done) { \
        asm volatile("{\n\t.reg .pred P1;\n\t" \
            "WL_%=:\n\t" \
            "mbarrier.try_wait.parity.acquire.cta.shared::cta.b64 P1, [%0], %1, 0x989680;\n\t" \
            "@P1 bra.uni WD_%=;\n\t" \
            "bra.uni WL_%=;\n\t" \
            "WD_%=:\n\t}" :: "r"(_mbar), "r"(_p) : "memory"); \
    } \
} while (0)
__device__ __forceinline__ void tma_load_2d(uint32_t smem_addr, const void* tmap,
                                            int cx, int cy, uint32_t mbar) {
    asm volatile(
        "cp.async.bulk.tensor.2d.shared::cta.global.tile.mbarrier::complete_tx::bytes "
        "[%0], [%1, {%2, %3}], [%4];"
        :: "r"(smem_addr), "l"(tmap), "r"(cx), "r"(cy), "r"(mbar)
        : "memory");
}

// smem: mbarriers [0,32); A at 1024 (64KB); B at 66560 (3 x 16KB)
#define SM_MB    0
#define SMEM_A   1024
#define SMEM_B   66560
#define SMEM_TOT 115712

// ---------------------------------------------------------------------------
// K0 (fused prologue): role by blockIdx.
// ---------------------------------------------------------------------------
#define RT_T  8192
#define RT_E  (RT_T + 2048)
#define RT_N  (RT_E + 32)
#define RT_I  (RT_N + 8192)

__global__ void prep_kernel(const float* __restrict__ in,
                            const float* __restrict__ embed,
                            const float* __restrict__ ema,
                            float* __restrict__ out) {
    __shared__ float tile[32][33];
    int bid = blockIdx.x;
    int t = threadIdx.x;
    if (bid < RT_T) {
        int hx = bid & 31, dy = (bid >> 5) & 7, b = bid >> 8;
        int d0 = dy * 32, h0 = hx * 32;
        int tx = t & 31, ty = t >> 5;     // 32 x 8
        const float* src = in + (size_t)b * DD * HW;
#pragma unroll
        for (int i = 0; i < 32; i += 8)
            tile[ty + i][tx] = src[(d0 + ty + i) * HW + h0 + tx];
        __syncthreads();
#pragma unroll
        for (int i = 0; i < 32; i += 8) {
            float v = tile[tx][ty + i];
            size_t o = (size_t)(b * HW + h0 + ty + i) * DD + d0 + tx;
            g_X[o]  = v;
            g_Xf[o] = __float2half_rn(v);
        }
    } else if (bid < RT_E) {
        int rb = bid - RT_T;
        int kx = rb & 255, dy = rb >> 8;
        int k0 = kx * 32, d0 = dy * 32;
        int tx = t & 31, ty = t >> 5;
#pragma unroll
        for (int i = 0; i < 32; i += 8)
            tile[ty + i][tx] = embed[(size_t)(d0 + ty + i) * KK + k0 + tx];
        __syncthreads();
#pragma unroll
        for (int i = 0; i < 32; i += 8) {
            float v = tile[tx][ty + i];
            size_t o = (size_t)(k0 + ty + i) * DD + d0 + tx;
            g_EtF[o] = v;
            g_Ef[o]  = __float2half_rn(v);
        }
    } else if (bid < RT_N) {
        int k = (bid - RT_E) * 256 + t;
        float s = 0.f;
        double sd = 0.0;
#pragma unroll 8
        for (int d = 0; d < DD; d++) {
            float v = embed[(size_t)d * KK + k];
            s = fmaf(v, v, s);
            sd = fma((double)v, (double)v, sd);
        }
        g_enorm[k]  = s;
        g_enormd[k] = sd;
    } else {
        int i = (bid - RT_N) * 256 + t;
        out[NEWEMA_OFF + i] = 0.99f * ema[i];
        if (i < KK)  g_counts[i] = 0.f;
        if (i < 4)   g_scal[i]   = 0.f;
    }
}

// ---------------------------------------------------------------------------
// K2: fp16 mma.sync argmin (fp32 acc), TMA staging. CTA = 128 rows x 2048-code
// slice. 8 warps (2x4). Triple-buffered B, one barrier per iteration.
// ---------------------------------------------------------------------------
__global__ __launch_bounds__(256, 2) void argmin_mma_kernel(
        const __grid_constant__ CUtensorMap tmA,
        const __grid_constant__ CUtensorMap tmB) {
    extern __shared__ char smem[];
    uint32_t sb = smem_to_u32(smem);
    int tid  = threadIdx.x;
    int lane = tid & 31, wid = tid >> 5;
    int wm = wid >> 2, wn = wid & 3;
    int mt = blockIdx.x >> 2, slice = blockIdx.x & 3;
    int n0 = mt * 128;
    int cs0 = slice * KPS;

    if (tid == 0) {
        MBARRIER_INIT(sb + SM_MB + 0,  1);   // B buf 0
        MBARRIER_INIT(sb + SM_MB + 8,  1);   // B buf 1
        MBARRIER_INIT(sb + SM_MB + 16, 1);   // B buf 2
        MBARRIER_INIT(sb + SM_MB + 24, 1);   // A
    }
    __syncthreads();

    if (tid == 0) {
        MBARRIER_EXPECT_TX(sb + SM_MB + 24, 65536);
#pragma unroll
        for (int kc = 0; kc < 4; ++kc)
            tma_load_2d(sb + SMEM_A + kc * 16384, &tmA, kc * 64, n0, sb + SM_MB + 24);
        MBARRIER_EXPECT_TX(sb + SM_MB + 0, 16384);
        tma_load_2d(sb + SMEM_B + 0, &tmB, 0, cs0, sb + SM_MB + 0);
        MBARRIER_EXPECT_TX(sb + SM_MB + 8, 16384);
        tma_load_2d(sb + SMEM_B + 16384, &tmB, 64, cs0, sb + SM_MB + 8);
    }

    float acc[4][4][4];
#pragma unroll
    for (int m = 0; m < 4; ++m)
#pragma unroll
        for (int n = 0; n < 4; ++n)
#pragma unroll
            for (int q = 0; q < 4; ++q) acc[m][n][q] = 0.f;

    float t1v[8], t2v[8];
    int   t1i[8], t2i[8];
#pragma unroll
    for (int s = 0; s < 8; ++s) { t1v[s] = 3.4e38f; t2v[s] = 3.4e38f; t1i[s] = 0; t2i[s] = 0; }

    int j   = lane >> 3, rwi = lane & 7;
    int arow = wm * 64 + rwi + ((j & 1) << 3);
    int agsel = j >> 1;
    int arx  = arow & 7;
    uint32_t aBase = sb + SMEM_A + (uint32_t)arow * 128;
    int crow = wn * 32 + ((j >> 1) << 3) + rwi;
    int bgsel = j & 1;
    int crx  = crow & 7;
    uint32_t bBase = sb + SMEM_B + (uint32_t)crow * 128;

    int tid4 = lane & 3;

    MBARRIER_WAIT_PARITY(sb + SM_MB + 24, 0);

#pragma unroll 1
    for (int it = 0; it < NIT; ++it) {
        int kc = it & 3;
        int buf = it % 3;
        MBARRIER_WAIT_PARITY(sb + SM_MB + buf * 8, (it / 3) & 1);
        __syncthreads();
        if (tid == 0 && it + 2 < NIT) {
            int it2 = it + 2;
            int b2 = it2 % 3;
            MBARRIER_EXPECT_TX(sb + SM_MB + b2 * 8, 16384);
            tma_load_2d(sb + SMEM_B + b2 * 16384, &tmB,
                        (it2 & 3) * 64, cs0 + (it2 >> 2) * 128, sb + SM_MB + b2 * 8);
        }

#pragma unroll
        for (int kk = 0; kk < 4; ++kk) {
            uint32_t ah[4][4], bh[2][4];
            uint32_t ga = (uint32_t)(((2 * kk + agsel) ^ arx) << 4);
            uint32_t gb = (uint32_t)(((2 * kk + bgsel) ^ crx) << 4);
#pragma unroll
            for (int m = 0; m < 4; ++m)
                ldsm4(ah[m], aBase + kc * 16384 + m * 2048 + ga);
#pragma unroll
            for (int np = 0; np < 2; ++np)
                ldsm4(bh[np], bBase + buf * 16384 + np * 2048 + gb);
#pragma unroll
            for (int m = 0; m < 4; ++m)
#pragma unroll
                for (int n = 0; n < 4; ++n)
                    mma16816(acc[m][n], ah[m], &bh[n >> 1][(n & 1) * 2]);
        }

        if (kc == 3) {
            int nt = it >> 2;
            int cb = cs0 + nt * 128 + wn * 32 + tid4 * 2;
#pragma unroll
            for (int m = 0; m < 4; ++m) {
#pragma unroll
                for (int n = 0; n < 4; ++n) {
                    int c = cb + n * 8;
                    float2 en = *(const float2*)&g_enorm[c];
                    float d0 = fmaf(-2.f, acc[m][n][0], en.x);
                    float d1 = fmaf(-2.f, acc[m][n][1], en.y);
                    float d2 = fmaf(-2.f, acc[m][n][2], en.x);
                    float d3 = fmaf(-2.f, acc[m][n][3], en.y);
                    int s0 = m * 2, s1 = m * 2 + 1;
                    if (d0 < t1v[s0]) { t2v[s0] = t1v[s0]; t2i[s0] = t1i[s0]; t1v[s0] = d0; t1i[s0] = c; }
                    else if (d0 < t2v[s0]) { t2v[s0] = d0; t2i[s0] = c; }
                    if (d1 < t1v[s0]) { t2v[s0] = t1v[s0]; t2i[s0] = t1i[s0]; t1v[s0] = d1; t1i[s0] = c + 1; }
                    else if (d1 < t2v[s0]) { t2v[s0] = d1; t2i[s0] = c + 1; }
                    if (d2 < t1v[s1]) { t2v[s1] = t1v[s1]; t2i[s1] = t1i[s1]; t1v[s1] = d2; t1i[s1] = c; }
                    else if (d2 < t2v[s1]) { t2v[s1] = d2; t2i[s1] = c; }
                    if (d3 < t1v[s1]) { t2v[s1] = t1v[s1]; t2i[s1] = t1i[s1]; t1v[s1] = d3; t1i[s1] = c + 1; }
                    else if (d3 < t2v[s1]) { t2v[s1] = d3; t2i[s1] = c + 1; }
#pragma unroll
                    for (int q = 0; q < 4; ++q) acc[m][n][q] = 0.f;
                }
            }
        }
    }

#pragma unroll
    for (int s = 0; s < 8; ++s) {
        float v1 = t1v[s], v2 = t2v[s];
        int   i1 = t1i[s], i2 = t2i[s];
#pragma unroll
        for (int off = 1; off <= 2; off <<= 1) {
            float ov1 = __shfl_xor_sync(0xffffffffu, v1, off);
            int   oi1 = __shfl_xor_sync(0xffffffffu, i1, off);
            float ov2 = __shfl_xor_sync(0xffffffffu, v2, off);
            int   oi2 = __shfl_xor_sync(0xffffffffu, i2, off);
            if (ov1 < v1 || (ov1 == v1 && oi1 < i1)) {
                float nv2; int ni2;
                if (v1 < ov2 || (v1 == ov2 && i1 < oi2)) { nv2 = v1; ni2 = i1; }
                else { nv2 = ov2; ni2 = oi2; }
                v1 = ov1; i1 = oi1; v2 = nv2; i2 = ni2;
            } else {
                if (ov1 < v2 || (ov1 == v2 && oi1 < i2)) { v2 = ov1; i2 = oi1; }
            }
        }
        if (tid4 == 0) {
            int grp = lane >> 2;
            int row = n0 + wm * 64 + (s >> 1) * 16 + (s & 1) * 8 + grp;
            int slot = slice * 4 + wn;
            g_sv1[row * KSLOT + slot] = v1;
            g_si1[row * KSLOT + slot] = i1;
            g_sv2[row * KSLOT + slot] = v2;
            g_si2[row * KSLOT + slot] = i2;
        }
    }
}

// ---------------------------------------------------------------------------
// K2c: fused merge + compensated-fp32 rerank + dw scatter + loss (1 warp/row).
// ---------------------------------------------------------------------------
__global__ void rerank_kernel(float* __restrict__ out) {
    __shared__ double sl[8];
    int wid  = threadIdx.x >> 5;
    int lane = threadIdx.x & 31;
    int row  = blockIdx.x * 8 + wid;

    float v; int idx;
    if (lane < 16) { v = g_sv1[row * KSLOT + lane];        idx = g_si1[row * KSLOT + lane]; }
    else           { v = g_sv2[row * KSLOT + (lane - 16)]; idx = g_si2[row * KSLOT + (lane - 16)]; }

    int cand[4];
#pragma unroll
    for (int c = 0; c < 4; ++c) {
        float bv = v; int bi = idx;
#pragma unroll
        for (int o = 16; o; o >>= 1) {
            float ov = __shfl_xor_sync(0xffffffffu, bv, o);
            int   oi = __shfl_xor_sync(0xffffffffu, bi, o);
            if (ov < bv || (ov == bv && oi < bi)) { bv = ov; bi = oi; }
        }
        cand[c] = bi;
        if (v == bv && idx == bi) v = 3.4e38f;   // retire winner
    }

    const float4* xp = (const float4*)&g_X[(size_t)row * DD + lane * 8];
    float4 xa = xp[0], xb = xp[1];
    float Sp[4], Se[4];
#pragma unroll
    for (int c = 0; c < 4; ++c) {
        const float4* ep = (const float4*)&g_EtF[(size_t)cand[c] * DD + lane * 8];
        float4 ea = ep[0], eb = ep[1];
        float p, sp = 0.f, se = 0.f;
        p = xa.x * ea.x; se += fmaf(xa.x, ea.x, -p); sp += p;
        p = xa.y * ea.y; se += fmaf(xa.y, ea.y, -p); sp += p;
        p = xa.z * ea.z; se += fmaf(xa.z, ea.z, -p); sp += p;
        p = xa.w * ea.w; se += fmaf(xa.w, ea.w, -p); sp += p;
        p = xb.x * eb.x; se += fmaf(xb.x, eb.x, -p); sp += p;
        p = xb.y * eb.y; se += fmaf(xb.y, eb.y, -p); sp += p;
        p = xb.z * eb.z; se += fmaf(xb.z, eb.z, -p); sp += p;
        p = xb.w * eb.w; se += fmaf(xb.w, eb.w, -p); sp += p;
        Sp[c] = sp; Se[c] = se;
    }
    // ||x||^2 (compensated)
    float Xp, Xe;
    {
        float p, sp = 0.f, se = 0.f;
        p = xa.x * xa.x; se += fmaf(xa.x, xa.x, -p); sp += p;
        p = xa.y * xa.y; se += fmaf(xa.y, xa.y, -p); sp += p;
        p = xa.z * xa.z; se += fmaf(xa.z, xa.z, -p); sp += p;
        p = xa.w * xa.w; se += fmaf(xa.w, xa.w, -p); sp += p;
        p = xb.x * xb.x; se += fmaf(xb.x, xb.x, -p); sp += p;
        p = xb.y * xb.y; se += fmaf(xb.y, xb.y, -p); sp += p;
        p = xb.z * xb.z; se += fmaf(xb.z, xb.z, -p); sp += p;
        p = xb.w * xb.w; se += fmaf(xb.w, xb.w, -p); sp += p;
        Xp = sp; Xe = se;
    }
#pragma unroll
    for (int o = 16; o; o >>= 1) {
#pragma unroll
        for (int c = 0; c < 4; ++c) {
            Sp[c] += __shfl_down_sync(0xffffffffu, Sp[c], o);
            Se[c] += __shfl_down_sync(0xffffffffu, Se[c], o);
        }
        Xp += __shfl_down_sync(0xffffffffu, Xp, o);
        Xe += __shfl_down_sync(0xffffffffu, Xe, o);
    }
    int bi = 0;
    if (lane == 0) {
        double bv = 1e300;
        bi = cand[0];
#pragma unroll
        for (int c = 0; c < 4; ++c) {
            double d = g_enormd[cand[c]] - 2.0 * ((double)Sp[c] + (double)Se[c]);
            if (d < bv || (d == bv && cand[c] < bi)) { bv = d; bi = cand[c]; }
        }
        g_idx[row] = bi;
        atomicAdd(&g_counts[bi], 1.0f);
        sl[wid] = bv + (double)Xp + (double)Xe;   // exact dist of chosen code
    }
    bi = __shfl_sync(0xffffffffu, bi, 0);

    // fused dw scatter: this warp holds x[row][lane*8 .. lane*8+7]
    int d0 = lane * 8;
    float* base = out + NEWEMA_OFF + bi;
    atomicAdd(base + (size_t)(d0 + 0) * KK, 0.01f * xa.x);
    atomicAdd(base + (size_t)(d0 + 1) * KK, 0.01f * xa.y);
    atomicAdd(base + (size_t)(d0 + 2) * KK, 0.01f * xa.z);
    atomicAdd(base + (size_t)(d0 + 3) * KK, 0.01f * xa.w);
    atomicAdd(base + (size_t)(d0 + 4) * KK, 0.01f * xb.x);
    atomicAdd(base + (size_t)(d0 + 5) * KK, 0.01f * xb.y);
    atomicAdd(base + (size_t)(d0 + 6) * KK, 0.01f * xb.z);
    atomicAdd(base + (size_t)(d0 + 7) * KK, 0.01f * xb.w);

    __syncthreads();
    if (threadIdx.x == 0) {
        double s = 0.0;
#pragma unroll
        for (int i = 0; i < 8; ++i) s += sl[i];
        atomicAdd(&g_scal[0], (float)s);
    }
}

// ---------------------------------------------------------------------------
// K4: gather quantize -> out (NCHW). grid 1024: b = bid>>5, 8 d's per block.
// ---------------------------------------------------------------------------
__global__ void gather_kernel(const float* __restrict__ embed,
                              float* __restrict__ out) {
    __shared__ int sidx[HW];
    int b  = blockIdx.x >> 5;
    int d0 = (blockIdx.x & 31) * 8;
    int t  = threadIdx.x;

    for (int i = t; i < HW; i += 256) sidx[i] = g_idx[b * HW + i];
    __syncthreads();

#pragma unroll
    for (int d = d0; d < d0 + 8; d++) {
        const float* erow = embed + (size_t)d * KK;
        float* orow = out + OUT_OFF + (size_t)b * DD * HW + (size_t)d * HW;
#pragma unroll
        for (int hw = t; hw < HW; hw += 256)
            orow[hw] = erow[sidx[hw]];
    }
}

// ---------------------------------------------------------------------------
// K6: finalize scalars + new_cluster_size + 1/smoothed
// ---------------------------------------------------------------------------
__global__ void finalize_kernel(const float* __restrict__ cs, float* __restrict__ out) {
    __shared__ float sh[32];
    __shared__ float s_n;
    int t = threadIdx.x;
    float ncs_loc[8];
    float nsum = 0.f, psum = 0.f;
#pragma unroll
    for (int i = 0; i < 8; i++) {
        int k = t + i * 1024;
        float c = g_counts[k];
        float v = cs[k] * 0.99f + 0.01f * c;
        out[NCS_OFF + k] = v;
        ncs_loc[i] = v;
        nsum += v;
        float p = c * (1.0f / 32768.0f);
        psum += p * logf(p + 1e-10f);
    }
#pragma unroll
    for (int o = 16; o; o >>= 1) nsum += __shfl_down_sync(0xffffffffu, nsum, o);
    if ((t & 31) == 0) sh[t >> 5] = nsum;
    __syncthreads();
    if (t < 32) {
        float v = sh[t];
#pragma unroll
        for (int o = 16; o; o >>= 1) v += __shfl_down_sync(0xffffffffu, v, o);
        if (t == 0) s_n = v;
    }
    __syncthreads();
    float n = s_n;
#pragma unroll
    for (int i = 0; i < 8; i++) {
        int k = t + i * 1024;
        float v = ncs_loc[i];
        g_invsm[k] = (n + v * 1e-5f) / (n * (v + 1e-5f));
    }
    __syncthreads();
#pragma unroll
    for (int o = 16; o; o >>= 1) psum += __shfl_down_sync(0xffffffffu, psum, o);
    if ((t & 31) == 0) sh[t >> 5] = psum;
    __syncthreads();
    if (t == 0) {
        float p = 0.f;
#pragma unroll
        for (int i = 0; i < 32; i++) p += sh[i];
        out[LOSS_OFF] = 0.25f * g_scal[0] * (1.0f / 8388608.0f);
        out[PERP_OFF] = expf(-p);
    }
}

// ---------------------------------------------------------------------------
// K7: new_embed = new_ema_embed * (1/smoothed)
// ---------------------------------------------------------------------------
__global__ void newembed_kernel(float* __restrict__ out) {
    int i = blockIdx.x * 256 + threadIdx.x;
    int k = i & (KK - 1);
    out[NEWEMB_OFF + i] = out[NEWEMA_OFF + i] * g_invsm[k];
}

// ---------------------------------------------------------------------------
typedef CUresult (*PFN_tmec)(CUtensorMap*, CUtensorMapDataType, cuuint32_t,
                             void*, const cuuint64_t*, const cuuint64_t*,
                             const cuuint32_t*, const cuuint32_t*,
                             CUtensorMapInterleave, CUtensorMapSwizzle,
                             CUtensorMapL2promotion, CUtensorMapFloatOOBfill);

extern "C" void kernel_launch(void* const* d_in, const int* in_sizes, int n_in,
                              void* d_out, int out_size) {
    const float* inputs = (const float*)d_in[0];
    const float* embed  = (const float*)d_in[1];
    const float* cs     = (const float*)d_in[2];
    const float* ema    = (const float*)d_in[3];
    float* out = (float*)d_out;
    (void)in_sizes; (void)n_in; (void)out_size;

    // --- build TMA tensormaps (host-side; baked into graph at capture) ---
    void* fnp = nullptr;
    cudaDriverEntryPointQueryResult qr;
    cudaGetDriverEntryPointByVersion("cuTensorMapEncodeTiled", &fnp, 12000,
                                     cudaEnableDefault, &qr);
    PFN_tmec encode = (PFN_tmec)fnp;

    void *pXf = nullptr, *pEf = nullptr;
    cudaGetSymbolAddress(&pXf, g_Xf);
    cudaGetSymbolAddress(&pEf, g_Ef);

    CUtensorMap tmA, tmB;
    {
        cuuint64_t dims[2]  = {256, 32768};
        cuuint64_t strides[1] = {512};
        cuuint32_t box[2]   = {64, 128};
        cuuint32_t es[2]    = {1, 1};
        encode(&tmA, CU_TENSOR_MAP_DATA_TYPE_FLOAT16, 2, pXf, dims, strides,
               box, es, CU_TENSOR_MAP_INTERLEAVE_NONE, CU_TENSOR_MAP_SWIZZLE_128B,
               CU_TENSOR_MAP_L2_PROMOTION_L2_128B, CU_TENSOR_MAP_FLOAT_OOB_FILL_NONE);
    }
    {
        cuuint64_t dims[2]  = {256, 8192};
        cuuint64_t strides[1] = {512};
        cuuint32_t box[2]   = {64, 128};
        cuuint32_t es[2]    = {1, 1};
        encode(&tmB, CU_TENSOR_MAP_DATA_TYPE_FLOAT16, 2, pEf, dims, strides,
               box, es, CU_TENSOR_MAP_INTERLEAVE_NONE, CU_TENSOR_MAP_SWIZZLE_128B,
               CU_TENSOR_MAP_L2_PROMOTION_L2_128B, CU_TENSOR_MAP_FLOAT_OOB_FILL_NONE);
    }

    cudaFuncSetAttribute(argmin_mma_kernel,
                         cudaFuncAttributeMaxDynamicSharedMemorySize, SMEM_TOT);

    prep_kernel<<<RT_I, 256>>>(inputs, embed, ema, out);
    argmin_mma_kernel<<<(NN / 128) * KSPLIT, 256, SMEM_TOT>>>(tmA, tmB);
    rerank_kernel<<<NN / 8, 256>>>(out);
    gather_kernel<<<1024, 256>>>(embed, out);
    finalize_kernel<<<1, 1024>>>(cs, out);
    newembed_kernel<<<(DD * KK) / 256, 256>>>(out);
}